// round 1
// baseline (speedup 1.0000x reference)
#include <cuda_runtime.h>
#include <cstdint>
#include <cstddef>

#define BB 64
#define TT 512
#define DD 512
#define JT 4
#define NBLK (DD / JT) /* 128 CTAs for the scan — one wave, co-resident */

// ---------------- scratch (static device allocations are allowed) ----------
// Preactivations transposed: g_pre[z][t][o][b], z in {Xi, Xc, Xo}
__device__ float g_pre[3][(size_t)TT * DD * BB]; // 3 x 64 MB
// h double-buffered, transposed [j][b]
__device__ float g_hT[2][DD * BB];
// grid barrier state (count returns to 0 after each full barrier; sense is
// monotonic, only compared relatively -> deterministic across graph replays)
__device__ unsigned int g_count;
__device__ volatile unsigned int g_sense;

__device__ __forceinline__ void grid_barrier(unsigned nblk) {
    __syncthreads();
    __threadfence();
    if (threadIdx.x == 0) {
        unsigned s = g_sense;
        if (atomicAdd(&g_count, 1u) == nblk - 1u) {
            g_count = 0u;
            __threadfence();
            g_sense = s + 1u;
        } else {
            while (g_sense == s) { __nanosleep(64); }
        }
    }
    __syncthreads();
    __threadfence();
}

// ---------------- Phase 1: Xi/Xc/Xo = X @ W^T + b, output [T][O][B] --------
__global__ void __launch_bounds__(256, 2)
gemm_pre_kernel(const float* __restrict__ X,
                const float* __restrict__ Wi, const float* __restrict__ bi,
                const float* __restrict__ Wc, const float* __restrict__ bc,
                const float* __restrict__ Wo, const float* __restrict__ bo)
{
    __shared__ float As[8][128];
    __shared__ float Bs[8][128];

    const int z = blockIdx.z;
    const float* W   = (z == 0) ? Wi : (z == 1) ? Wc : Wo;
    const float* bia = (z == 0) ? bi : (z == 1) ? bc : bo;
    float* out = g_pre[z];

    const int tid = threadIdx.x;
    const int mt = blockIdx.y;   // 256 tiles over M = B*T (m = t*B + b)
    const int nt = blockIdx.x;   // 4 tiles over N = DOUT

    const int lrow = tid >> 1;           // 0..127
    const int lk4  = (tid & 1) << 2;     // 0 or 4

    const int m_l = mt * 128 + lrow;     // m = t*64 + b
    const float* Arow = X + ((size_t)(m_l & 63) * TT + (size_t)(m_l >> 6)) * DD;
    const float* Brow = W + (size_t)(nt * 128 + lrow) * DD;

    const int ty = tid >> 4, tx = tid & 15;
    const int m0 = ty * 8, n0 = tx * 8;

    float acc[8][8];
#pragma unroll
    for (int i = 0; i < 8; i++)
#pragma unroll
        for (int jj = 0; jj < 8; jj++) acc[i][jj] = 0.f;

    for (int k0 = 0; k0 < DD; k0 += 8) {
        float4 a4 = *(const float4*)(Arow + k0 + lk4);
        float4 b4 = *(const float4*)(Brow + k0 + lk4);
        As[lk4 + 0][lrow] = a4.x;
        As[lk4 + 1][lrow] = a4.y;
        As[lk4 + 2][lrow] = a4.z;
        As[lk4 + 3][lrow] = a4.w;
        Bs[lk4 + 0][lrow] = b4.x;
        Bs[lk4 + 1][lrow] = b4.y;
        Bs[lk4 + 2][lrow] = b4.z;
        Bs[lk4 + 3][lrow] = b4.w;
        __syncthreads();
#pragma unroll
        for (int kk = 0; kk < 8; kk++) {
            float4 af0 = *(const float4*)&As[kk][m0];
            float4 af1 = *(const float4*)&As[kk][m0 + 4];
            float4 bf0 = *(const float4*)&Bs[kk][n0];
            float4 bf1 = *(const float4*)&Bs[kk][n0 + 4];
            float av[8] = {af0.x, af0.y, af0.z, af0.w, af1.x, af1.y, af1.z, af1.w};
            float bv[8] = {bf0.x, bf0.y, bf0.z, bf0.w, bf1.x, bf1.y, bf1.z, bf1.w};
#pragma unroll
            for (int i = 0; i < 8; i++)
#pragma unroll
                for (int jj = 0; jj < 8; jj++)
                    acc[i][jj] = fmaf(av[i], bv[jj], acc[i][jj]);
        }
        __syncthreads();
    }

    // epilogue: out[t][o][b] = acc + bias[o]; m0 % 8 == 0 keeps the 8-m run
    // inside one t (B = 64), so float4 over b is safe and aligned.
    const int mbase = mt * 128 + m0;
    const int tt = mbase >> 6;
    const int b0 = mbase & 63;
#pragma unroll
    for (int jj = 0; jj < 8; jj++) {
        const int o = nt * 128 + n0 + jj;
        const float bz = __ldg(&bia[o]);
        float* op = out + (size_t)tt * (DD * BB) + (size_t)o * BB + b0;
        float4 v0 = make_float4(acc[0][jj] + bz, acc[1][jj] + bz,
                                acc[2][jj] + bz, acc[3][jj] + bz);
        float4 v1 = make_float4(acc[4][jj] + bz, acc[5][jj] + bz,
                                acc[6][jj] + bz, acc[7][jj] + bz);
        *(float4*)op = v0;
        *(float4*)(op + 4) = v1;
    }
}

// ---------------- Phase 2: persistent LSTM scan ------------------------------
// 128 CTAs x 256 threads. CTA owns j0..j0+3 (all 4 gates). thread = (b, jl):
//   b = tid>>2 (0..63), jl = tid&3. c-state lives in a register for all 512
//   steps. U tile (4 gates x 4 rows x 512) lives in smem for all 512 steps.
// h exchanged through global (L2, .cg) with double buffering; one grid
// barrier per timestep.
__global__ void __launch_bounds__(256, 1)
lstm_scan_kernel(const float* __restrict__ Ui, const float* __restrict__ Uf,
                 const float* __restrict__ Uc, const float* __restrict__ Uo,
                 const float* __restrict__ bUf, const float* __restrict__ bUc,
                 const float* __restrict__ bUo,
                 float* __restrict__ outH, float* __restrict__ outC)
{
    extern __shared__ float sm[];
    float* U_s = sm;                   // [4][JT][DD] = 8192 floats (32 KB)
    float* h_s = sm + 4 * JT * DD;     // [DD][BB]    = 32768 floats (128 KB)

    const int tid = threadIdx.x;
    const int jl = tid & (JT - 1);
    const int b  = tid >> 2;
    const int j0 = blockIdx.x * JT;
    const int j  = j0 + jl;
    const unsigned nblk = gridDim.x;

    // Load my U tile once; it stays resident across all 512 steps.
    for (int idx = tid; idx < 4 * JT * DD; idx += 256) {
        const int g = idx / (JT * DD);
        const int r = (idx / DD) & (JT - 1);
        const int k = idx & (DD - 1);
        const float* U = (g == 0) ? Ui : (g == 1) ? Uf : (g == 2) ? Uc : Uo;
        U_s[idx] = __ldg(&U[(size_t)(j0 + r) * DD + k]);
    }

    const float bfb = __ldg(&bUf[j]);
    const float bcb = __ldg(&bUc[j]);
    const float bob = __ldg(&bUo[j]);

    // zero my slice of h buffer 0 (previous replay leaves it dirty)
    g_hT[0][(size_t)j0 * BB + tid] = 0.f;
    grid_barrier(nblk);

    const float* UiS = U_s + (0 * JT + jl) * DD;
    const float* UfS = U_s + (1 * JT + jl) * DD;
    const float* UcS = U_s + (2 * JT + jl) * DD;
    const float* UoS = U_s + (3 * JT + jl) * DD;

    float c = 0.f;

    for (int t = 0; t < TT; t++) {
        // stage h_prev (L2 -> smem), bypassing L1 (written by other SMs)
        const float4* src = (const float4*)g_hT[t & 1];
        float4* dst = (float4*)h_s;
#pragma unroll
        for (int i = 0; i < (DD * BB / 4) / 256; i++)
            dst[tid + i * 256] = __ldcg(src + tid + i * 256);

        // issue preactivation loads early (DRAM latency hidden by GEMM)
        const size_t pidx = (size_t)t * (DD * BB) + (size_t)j * BB + b;
        const float xi = __ldcg(&g_pre[0][pidx]);
        const float xc = __ldcg(&g_pre[1][pidx]);
        const float xo = __ldcg(&g_pre[2][pidx]);

        __syncthreads();

        float ai = 0.f, af = 0.f, ac = 0.f, ao = 0.f;
#pragma unroll 4
        for (int k = 0; k < DD; k += 4) {
            const float4 ui = *(const float4*)(UiS + k);
            const float4 uf = *(const float4*)(UfS + k);
            const float4 uc = *(const float4*)(UcS + k);
            const float4 uo = *(const float4*)(UoS + k);
            const float h0 = h_s[(k + 0) * BB + b];
            const float h1 = h_s[(k + 1) * BB + b];
            const float h2 = h_s[(k + 2) * BB + b];
            const float h3 = h_s[(k + 3) * BB + b];
            ai = fmaf(h0, ui.x, ai); ai = fmaf(h1, ui.y, ai);
            ai = fmaf(h2, ui.z, ai); ai = fmaf(h3, ui.w, ai);
            af = fmaf(h0, uf.x, af); af = fmaf(h1, uf.y, af);
            af = fmaf(h2, uf.z, af); af = fmaf(h3, uf.w, af);
            ac = fmaf(h0, uc.x, ac); ac = fmaf(h1, uc.y, ac);
            ac = fmaf(h2, uc.z, ac); ac = fmaf(h3, uc.w, ac);
            ao = fmaf(h0, uo.x, ao); ao = fmaf(h1, uo.y, ao);
            ao = fmaf(h2, uo.z, ao); ao = fmaf(h3, uo.w, ao);
        }

        // gates (note the reference quirk: f uses xi, and i has no U-bias)
        const float pi = xi + ai;
        const float pf = xi + af + bfb;
        const float pc = xc + ac + bcb;
        const float po = xo + ao + bob;
        const float ig = 1.f / (1.f + __expf(-pi));
        const float fg = 1.f / (1.f + __expf(-pf));
        const float gg = tanhf(pc);
        const float og = 1.f / (1.f + __expf(-po));
        c = fg * c + ig * gg;
        const float h = og * tanhf(c);

        // publish h for next step (other buffer), write outputs
        __stcg(&g_hT[(t + 1) & 1][(size_t)j * BB + b], h);
        const size_t oidx = (size_t)b * (TT * DD) + (size_t)t * DD + j;
        outH[oidx] = h;
        outC[oidx] = c;

        grid_barrier(nblk);
    }
}

// ---------------- launch -----------------------------------------------------
extern "C" void kernel_launch(void* const* d_in, const int* in_sizes, int n_in,
                              void* d_out, int out_size) {
    const float* X   = (const float*)d_in[0];
    const float* Wi  = (const float*)d_in[1];
    const float* bi  = (const float*)d_in[2];
    // d_in[3] = Wf, d_in[4] = bf: computed-but-unused in the reference; skipped
    const float* Wc  = (const float*)d_in[5];
    const float* bc  = (const float*)d_in[6];
    const float* Wo  = (const float*)d_in[7];
    const float* bo  = (const float*)d_in[8];
    const float* Ui  = (const float*)d_in[9];
    const float* Uf  = (const float*)d_in[10];
    const float* bUf = (const float*)d_in[11];
    const float* Uc  = (const float*)d_in[12];
    const float* bUc = (const float*)d_in[13];
    const float* Uo  = (const float*)d_in[14];
    const float* bUo = (const float*)d_in[15];

    float* outH = (float*)d_out;
    float* outC = outH + (size_t)BB * TT * DD;

    // Phase 1: input projections (Xi, Xc, Xo), transposed to [T][O][B]
    dim3 g1(DD / 128, (BB * TT) / 128, 3);
    gemm_pre_kernel<<<g1, 256>>>(X, Wi, bi, Wc, bc, Wo, bo);

    // Phase 2: persistent scan (128 CTAs = single wave, co-resident)
    const size_t smem = (size_t)(4 * JT * DD + DD * BB) * sizeof(float); // 160 KB
    cudaFuncSetAttribute(lstm_scan_kernel,
                         cudaFuncAttributeMaxDynamicSharedMemorySize, (int)smem);
    lstm_scan_kernel<<<NBLK, 256, smem>>>(Ui, Uf, Uc, Uo, bUf, bUc, bUo,
                                          outH, outC);
}

// round 2
// speedup vs baseline: 2.7845x; 2.7845x over previous
#include <cuda_runtime.h>
#include <cstdint>
#include <cstddef>

#define BB 64
#define TT 512
#define DD 512
#define JT 4
#define NBLK 128
#define HPAD 516   /* padded row stride (floats) -> conflict-free banks */

// ---------------- scratch ---------------------------------------------------
// Preactivations transposed: g_pre[z][t][j][b], z in {Xi, Xc, Xo}
__device__ float g_pre[3][(size_t)TT * DD * BB]; // 3 x 64 MB
// h double-buffered: g_h[buf][b][k]
__device__ float g_h[2][BB * DD];
// monotonic grid-barrier counter (zeroed by init kernel every replay)
__device__ unsigned int g_count;

// ---------------- init: zero counter + h buffer 0 ---------------------------
__global__ void init_kernel() {
    const int i = blockIdx.x * blockDim.x + threadIdx.x;
    if (i == 0) g_count = 0u;
    if (i < BB * DD) g_h[0][i] = 0.f;
}

// ---------------- Phase 1: Xi/Xc/Xo = X @ W^T + b, output [T][O][B] --------
__global__ void __launch_bounds__(256, 2)
gemm_pre_kernel(const float* __restrict__ X,
                const float* __restrict__ Wi, const float* __restrict__ bi,
                const float* __restrict__ Wc, const float* __restrict__ bc,
                const float* __restrict__ Wo, const float* __restrict__ bo)
{
    __shared__ float As[8][128];
    __shared__ float Bs[8][128];

    const int z = blockIdx.z;
    const float* W   = (z == 0) ? Wi : (z == 1) ? Wc : Wo;
    const float* bia = (z == 0) ? bi : (z == 1) ? bc : bo;
    float* out = g_pre[z];

    const int tid = threadIdx.x;
    const int mt = blockIdx.y;
    const int nt = blockIdx.x;

    const int lrow = tid >> 1;
    const int lk4  = (tid & 1) << 2;

    const int m_l = mt * 128 + lrow;     // m = t*64 + b
    const float* Arow = X + ((size_t)(m_l & 63) * TT + (size_t)(m_l >> 6)) * DD;
    const float* Brow = W + (size_t)(nt * 128 + lrow) * DD;

    const int ty = tid >> 4, tx = tid & 15;
    const int m0 = ty * 8, n0 = tx * 8;

    float acc[8][8];
#pragma unroll
    for (int i = 0; i < 8; i++)
#pragma unroll
        for (int jj = 0; jj < 8; jj++) acc[i][jj] = 0.f;

    for (int k0 = 0; k0 < DD; k0 += 8) {
        float4 a4 = *(const float4*)(Arow + k0 + lk4);
        float4 b4 = *(const float4*)(Brow + k0 + lk4);
        As[lk4 + 0][lrow] = a4.x;
        As[lk4 + 1][lrow] = a4.y;
        As[lk4 + 2][lrow] = a4.z;
        As[lk4 + 3][lrow] = a4.w;
        Bs[lk4 + 0][lrow] = b4.x;
        Bs[lk4 + 1][lrow] = b4.y;
        Bs[lk4 + 2][lrow] = b4.z;
        Bs[lk4 + 3][lrow] = b4.w;
        __syncthreads();
#pragma unroll
        for (int kk = 0; kk < 8; kk++) {
            float4 af0 = *(const float4*)&As[kk][m0];
            float4 af1 = *(const float4*)&As[kk][m0 + 4];
            float4 bf0 = *(const float4*)&Bs[kk][n0];
            float4 bf1 = *(const float4*)&Bs[kk][n0 + 4];
            float av[8] = {af0.x, af0.y, af0.z, af0.w, af1.x, af1.y, af1.z, af1.w};
            float bv[8] = {bf0.x, bf0.y, bf0.z, bf0.w, bf1.x, bf1.y, bf1.z, bf1.w};
#pragma unroll
            for (int i = 0; i < 8; i++)
#pragma unroll
                for (int jj = 0; jj < 8; jj++)
                    acc[i][jj] = fmaf(av[i], bv[jj], acc[i][jj]);
        }
        __syncthreads();
    }

    const int mbase = mt * 128 + m0;
    const int tt = mbase >> 6;
    const int b0 = mbase & 63;
#pragma unroll
    for (int jj = 0; jj < 8; jj++) {
        const int o = nt * 128 + n0 + jj;
        const float bz = __ldg(&bia[o]);
        float* op = out + (size_t)tt * (DD * BB) + (size_t)o * BB + b0;
        float4 v0 = make_float4(acc[0][jj] + bz, acc[1][jj] + bz,
                                acc[2][jj] + bz, acc[3][jj] + bz);
        float4 v1 = make_float4(acc[4][jj] + bz, acc[5][jj] + bz,
                                acc[6][jj] + bz, acc[7][jj] + bz);
        *(float4*)op = v0;
        *(float4*)(op + 4) = v1;
    }
}

// ---------------- grid barrier primitives ----------------------------------
__device__ __forceinline__ void bar_arrive() {
    asm volatile("red.release.gpu.add.u32 [%0], 1;" :: "l"(&g_count) : "memory");
}
__device__ __forceinline__ void bar_wait(unsigned target) {
    unsigned v;
    do {
        asm volatile("ld.acquire.gpu.u32 %0, [%1];" : "=r"(v) : "l"(&g_count) : "memory");
    } while (v < target);
}

// ---------------- Phase 2: persistent LSTM scan ------------------------------
// 128 CTAs x 256 threads, 1 CTA/SM. CTA owns j0..j0+3 across all 4 gates.
// thread = (b, jl): b = tid>>2, jl = tid&3. c in a register for all 512 steps.
// U tile (16 rows x 512, padded stride 516) resident in smem. h staged each
// step from L2 into smem as [b][k] (padded), conflict-free reads.
__global__ void __launch_bounds__(256, 1)
lstm_scan_kernel(const float* __restrict__ Ui, const float* __restrict__ Uf,
                 const float* __restrict__ Uc, const float* __restrict__ Uo,
                 const float* __restrict__ bUf, const float* __restrict__ bUc,
                 const float* __restrict__ bUo,
                 float* __restrict__ outH, float* __restrict__ outC)
{
    extern __shared__ float sm[];
    float* U_s = sm;                    // [16][HPAD]
    float* h_s = sm + 16 * HPAD;        // [64][HPAD]

    const int tid = threadIdx.x;
    const int jl = tid & 3;
    const int b  = tid >> 2;
    const int j0 = blockIdx.x * JT;
    const int j  = j0 + jl;

    // Load U tile once (resident for all steps). row = g*4 + r.
    for (int idx = tid; idx < 16 * DD; idx += 256) {
        const int row = idx >> 9;        // 0..15
        const int k   = idx & 511;
        const int g = row >> 2, r = row & 3;
        const float* U = (g == 0) ? Ui : (g == 1) ? Uf : (g == 2) ? Uc : Uo;
        U_s[row * HPAD + k] = __ldg(&U[(size_t)(j0 + r) * DD + k]);
    }

    const float bfb = __ldg(&bUf[j]);
    const float bcb = __ldg(&bUc[j]);
    const float bob = __ldg(&bUo[j]);

    const float* UiS = U_s + (0 * 4 + jl) * HPAD;
    const float* UfS = U_s + (1 * 4 + jl) * HPAD;
    const float* UcS = U_s + (2 * 4 + jl) * HPAD;
    const float* UoS = U_s + (3 * 4 + jl) * HPAD;

    float c = 0.f;

    // preload preactivations for t = 0
    float xi = __ldcg(&g_pre[0][(size_t)j * BB + b]);
    float xc = __ldcg(&g_pre[1][(size_t)j * BB + b]);
    float xo = __ldcg(&g_pre[2][(size_t)j * BB + b]);

    for (int t = 0; t < TT; t++) {
        // stage h_prev (L2 -> smem [b][k], padded). src layout [b][k] flat.
        {
            const float4* src = (const float4*)g_h[t & 1];
            float4* dst = (float4*)h_s;
#pragma unroll
            for (int i = 0; i < 32; i++) {
                const int m = tid + i * 256;       // 0..8191 float4s
                const int bb = m >> 7;             // b
                const int kq = m & 127;            // k/4
                dst[bb * (HPAD / 4) + kq] = __ldcg(src + m);
            }
        }
        __syncthreads();

        float ai0 = 0.f, ai1 = 0.f, af0 = 0.f, af1 = 0.f;
        float ac0 = 0.f, ac1 = 0.f, ao0 = 0.f, ao1 = 0.f;
        const float* hb = h_s + b * HPAD;

        for (int k = 0; k < DD; k += 16) {
            const float4 h0 = *(const float4*)(hb + k);
            const float4 h1 = *(const float4*)(hb + k + 4);
            const float4 h2 = *(const float4*)(hb + k + 8);
            const float4 h3 = *(const float4*)(hb + k + 12);
            float4 u;
#define DOT4(ACC, U4, H4) \
            ACC = fmaf((H4).x, (U4).x, ACC); ACC = fmaf((H4).y, (U4).y, ACC); \
            ACC = fmaf((H4).z, (U4).z, ACC); ACC = fmaf((H4).w, (U4).w, ACC);
            u = *(const float4*)(UiS + k);      DOT4(ai0, u, h0)
            u = *(const float4*)(UiS + k + 4);  DOT4(ai1, u, h1)
            u = *(const float4*)(UiS + k + 8);  DOT4(ai0, u, h2)
            u = *(const float4*)(UiS + k + 12); DOT4(ai1, u, h3)
            u = *(const float4*)(UfS + k);      DOT4(af0, u, h0)
            u = *(const float4*)(UfS + k + 4);  DOT4(af1, u, h1)
            u = *(const float4*)(UfS + k + 8);  DOT4(af0, u, h2)
            u = *(const float4*)(UfS + k + 12); DOT4(af1, u, h3)
            u = *(const float4*)(UcS + k);      DOT4(ac0, u, h0)
            u = *(const float4*)(UcS + k + 4);  DOT4(ac1, u, h1)
            u = *(const float4*)(UcS + k + 8);  DOT4(ac0, u, h2)
            u = *(const float4*)(UcS + k + 12); DOT4(ac1, u, h3)
            u = *(const float4*)(UoS + k);      DOT4(ao0, u, h0)
            u = *(const float4*)(UoS + k + 4);  DOT4(ao1, u, h1)
            u = *(const float4*)(UoS + k + 8);  DOT4(ao0, u, h2)
            u = *(const float4*)(UoS + k + 12); DOT4(ao1, u, h3)
#undef DOT4
        }

        // gates (reference quirks: f uses xi; i has no U-bias)
        const float pi = xi + (ai0 + ai1);
        const float pf = xi + (af0 + af1) + bfb;
        const float pc = xc + (ac0 + ac1) + bcb;
        const float po = xo + (ao0 + ao1) + bob;
        const float ig = 1.f / (1.f + __expf(-pi));
        const float fg = 1.f / (1.f + __expf(-pf));
        const float gg = tanhf(pc);
        const float og = 1.f / (1.f + __expf(-po));
        c = fg * c + ig * gg;
        const float h = og * tanhf(c);

        // publish h for step t+1, then arrive at the grid barrier
        __stcg(&g_h[(t + 1) & 1][b * DD + j], h);
        __syncthreads();
        if (tid == 0) bar_arrive();

        // overlap with the wait: outputs + next-step preactivations
        const size_t oidx = (size_t)b * (TT * DD) + (size_t)t * DD + j;
        outH[oidx] = h;
        outC[oidx] = c;
        if (t + 1 < TT) {
            const size_t p2 = (size_t)(t + 1) * (DD * BB) + (size_t)j * BB + b;
            xi = __ldcg(&g_pre[0][p2]);
            xc = __ldcg(&g_pre[1][p2]);
            xo = __ldcg(&g_pre[2][p2]);
        }

        if (tid == 0) bar_wait((unsigned)(t + 1) * NBLK);
        __syncthreads();
    }
}

// ---------------- launch -----------------------------------------------------
extern "C" void kernel_launch(void* const* d_in, const int* in_sizes, int n_in,
                              void* d_out, int out_size) {
    const float* X   = (const float*)d_in[0];
    const float* Wi  = (const float*)d_in[1];
    const float* bi  = (const float*)d_in[2];
    // d_in[3] = Wf, d_in[4] = bf: computed-but-unused in the reference
    const float* Wc  = (const float*)d_in[5];
    const float* bc  = (const float*)d_in[6];
    const float* Wo  = (const float*)d_in[7];
    const float* bo  = (const float*)d_in[8];
    const float* Ui  = (const float*)d_in[9];
    const float* Uf  = (const float*)d_in[10];
    const float* bUf = (const float*)d_in[11];
    const float* Uc  = (const float*)d_in[12];
    const float* bUc = (const float*)d_in[13];
    const float* Uo  = (const float*)d_in[14];
    const float* bUo = (const float*)d_in[15];

    float* outH = (float*)d_out;
    float* outC = outH + (size_t)BB * TT * DD;

    init_kernel<<<128, 256>>>();

    dim3 g1(DD / 128, (BB * TT) / 128, 3);
    gemm_pre_kernel<<<g1, 256>>>(X, Wi, bi, Wc, bc, Wo, bo);

    const size_t smem = (size_t)(80 * HPAD) * sizeof(float); // 16+64 rows x 516
    cudaFuncSetAttribute(lstm_scan_kernel,
                         cudaFuncAttributeMaxDynamicSharedMemorySize, (int)smem);
    lstm_scan_kernel<<<NBLK, 256, smem>>>(Ui, Uf, Uc, Uo, bUf, bUc, bUo,
                                          outH, outC);
}

// round 3
// speedup vs baseline: 2.9953x; 1.0757x over previous
#include <cuda_runtime.h>
#include <cstdint>
#include <cstddef>

#define BB 64
#define TT 512
#define DD 512
#define NG 4          /* independent batch groups */
#define CPG 32        /* CTAs per group (j-partition) */
#define BPG 16        /* batch columns per group */
#define JPC 16        /* j rows per CTA */
#define PITCH2 514    /* row pitch in float2 units (padded) */
#define PITCHF (2*PITCH2)

// ---------------- scratch ---------------------------------------------------
__device__ float g_pre[3][(size_t)TT * DD * BB];   // [z][t][j][b]
__device__ float g_h[NG][2][DD][BPG];              // per-group h, double-buffered
__device__ unsigned int g_cnt[NG * 32];            // per-group counters, separated

// ---------------- init ------------------------------------------------------
__global__ void init_kernel() {
    const int i = blockIdx.x * blockDim.x + threadIdx.x;
    if (i < NG * 32) g_cnt[i] = 0u;
    // zero h buffer 0 for every group: NG*DD*BPG = 32768 floats
    if (i < NG * DD * BPG) {
        const int g = i / (DD * BPG);
        const int r = i % (DD * BPG);
        g_h[g][0][r / BPG][r % BPG] = 0.f;
    }
}

// ---------------- Phase 1: Xi/Xc/Xo = X @ W^T + b, output [T][O][B] --------
__global__ void __launch_bounds__(256, 2)
gemm_pre_kernel(const float* __restrict__ X,
                const float* __restrict__ Wi, const float* __restrict__ bi,
                const float* __restrict__ Wc, const float* __restrict__ bc,
                const float* __restrict__ Wo, const float* __restrict__ bo)
{
    __shared__ float As[8][128];
    __shared__ float Bs[8][128];

    const int z = blockIdx.z;
    const float* W   = (z == 0) ? Wi : (z == 1) ? Wc : Wo;
    const float* bia = (z == 0) ? bi : (z == 1) ? bc : bo;
    float* out = g_pre[z];

    const int tid = threadIdx.x;
    const int mt = blockIdx.y;
    const int nt = blockIdx.x;

    const int lrow = tid >> 1;
    const int lk4  = (tid & 1) << 2;

    const int m_l = mt * 128 + lrow;     // m = t*64 + b
    const float* Arow = X + ((size_t)(m_l & 63) * TT + (size_t)(m_l >> 6)) * DD;
    const float* Brow = W + (size_t)(nt * 128 + lrow) * DD;

    const int ty = tid >> 4, tx = tid & 15;
    const int m0 = ty * 8, n0 = tx * 8;

    float acc[8][8];
#pragma unroll
    for (int i = 0; i < 8; i++)
#pragma unroll
        for (int jj = 0; jj < 8; jj++) acc[i][jj] = 0.f;

    for (int k0 = 0; k0 < DD; k0 += 8) {
        float4 a4 = *(const float4*)(Arow + k0 + lk4);
        float4 b4 = *(const float4*)(Brow + k0 + lk4);
        As[lk4 + 0][lrow] = a4.x;
        As[lk4 + 1][lrow] = a4.y;
        As[lk4 + 2][lrow] = a4.z;
        As[lk4 + 3][lrow] = a4.w;
        Bs[lk4 + 0][lrow] = b4.x;
        Bs[lk4 + 1][lrow] = b4.y;
        Bs[lk4 + 2][lrow] = b4.z;
        Bs[lk4 + 3][lrow] = b4.w;
        __syncthreads();
#pragma unroll
        for (int kk = 0; kk < 8; kk++) {
            float4 af0 = *(const float4*)&As[kk][m0];
            float4 af1 = *(const float4*)&As[kk][m0 + 4];
            float4 bf0 = *(const float4*)&Bs[kk][n0];
            float4 bf1 = *(const float4*)&Bs[kk][n0 + 4];
            float av[8] = {af0.x, af0.y, af0.z, af0.w, af1.x, af1.y, af1.z, af1.w};
            float bv[8] = {bf0.x, bf0.y, bf0.z, bf0.w, bf1.x, bf1.y, bf1.z, bf1.w};
#pragma unroll
            for (int i = 0; i < 8; i++)
#pragma unroll
                for (int jj = 0; jj < 8; jj++)
                    acc[i][jj] = fmaf(av[i], bv[jj], acc[i][jj]);
        }
        __syncthreads();
    }

    const int mbase = mt * 128 + m0;
    const int tt = mbase >> 6;
    const int b0 = mbase & 63;
#pragma unroll
    for (int jj = 0; jj < 8; jj++) {
        const int o = nt * 128 + n0 + jj;
        const float bz = __ldg(&bia[o]);
        float* op = out + (size_t)tt * (DD * BB) + (size_t)o * BB + b0;
        float4 v0 = make_float4(acc[0][jj] + bz, acc[1][jj] + bz,
                                acc[2][jj] + bz, acc[3][jj] + bz);
        float4 v1 = make_float4(acc[4][jj] + bz, acc[5][jj] + bz,
                                acc[6][jj] + bz, acc[7][jj] + bz);
        *(float4*)op = v0;
        *(float4*)(op + 4) = v1;
    }
}

// ---------------- packed fp32x2 helpers -------------------------------------
__device__ __forceinline__ void fma2(unsigned long long& acc,
                                     unsigned long long a, unsigned long long b) {
    asm("fma.rn.f32x2 %0, %1, %2, %0;" : "+l"(acc) : "l"(a), "l"(b));
}

// ---------------- group barrier ----------------------------------------------
__device__ __forceinline__ void gbar_arrive(unsigned int* cnt) {
    asm volatile("red.release.gpu.add.u32 [%0], 1;" :: "l"(cnt) : "memory");
}
__device__ __forceinline__ void gbar_wait(unsigned int* cnt, unsigned target) {
    unsigned v;
    do {
        asm volatile("ld.acquire.gpu.u32 %0, [%1];" : "=r"(v) : "l"(cnt) : "memory");
    } while (v < target);
}

// ---------------- Phase 2: persistent grouped LSTM scan ---------------------
// 4 groups x 32 CTAs. Group g owns batch columns [16g, 16g+16). CTA owns 16 j
// rows (all 4 gates). thread = (jj, bl): jj = tid>>4, bl = tid&15.
// U stored in smem as gate-PAIRED float2 rows: (Ui,Uf) and (Uc,Uo) -> each
// fma.rn.f32x2 computes two gates at once. h staged per step as duplicated
// (h,h) pairs so the inner loop has no packing MOVs.
__global__ void __launch_bounds__(256, 1)
lstm_scan_kernel(const float* __restrict__ Ui, const float* __restrict__ Uf,
                 const float* __restrict__ Uc, const float* __restrict__ Uo,
                 const float* __restrict__ bUf, const float* __restrict__ bUc,
                 const float* __restrict__ bUo,
                 float* __restrict__ outH, float* __restrict__ outC)
{
    extern __shared__ float sm[];
    // layout (floats): UIF[16][1028] | UCO[16][1028] | HS[16][1028]
    const int UIF = 0;
    const int UCO = JPC * PITCHF;
    const int HS  = 2 * JPC * PITCHF;

    const int tid = threadIdx.x;
    const int jj  = tid >> 4;       // 0..15 (j row within CTA)
    const int bl  = tid & 15;       // 0..15 (batch col within group)
    const int g   = blockIdx.x >> 5;
    const int cig = blockIdx.x & 31;
    const int j0  = cig * JPC;
    const int j   = j0 + jj;
    const int bg  = g * BPG + bl;   // global batch index
    unsigned int* cnt = &g_cnt[g * 32];

    // Load U tiles once, gate-paired: (Ui,Uf) and (Uc,Uo) interleaved float2.
    for (int idx = tid; idx < JPC * DD; idx += 256) {
        const int r = idx >> 9;         // j row 0..15
        const int k = idx & 511;
        const size_t gi = (size_t)(j0 + r) * DD + k;
        ((float2*)(sm + UIF))[r * PITCH2 + k] = make_float2(__ldg(&Ui[gi]), __ldg(&Uf[gi]));
        ((float2*)(sm + UCO))[r * PITCH2 + k] = make_float2(__ldg(&Uc[gi]), __ldg(&Uo[gi]));
    }

    const float bfb = __ldg(&bUf[j]);
    const float bcb = __ldg(&bUc[j]);
    const float bob = __ldg(&bUo[j]);

    const float* hrow = sm + HS  + bl * PITCHF;
    const float* uifr = sm + UIF + jj * PITCHF;
    const float* ucor = sm + UCO + jj * PITCHF;

    float c = 0.f;

    // preload preactivations for t = 0
    float xi = __ldcg(&g_pre[0][(size_t)j * BB + bg]);
    float xc = __ldcg(&g_pre[1][(size_t)j * BB + bg]);
    float xo = __ldcg(&g_pre[2][(size_t)j * BB + bg]);

    for (int t = 0; t < TT; t++) {
        // ---- stage h (group slice, 32 KB) from L2, duplicated (h,h) --------
        {
            const float4* src = (const float4*)&g_h[g][t & 1][0][0]; // [512][16]
            float2* hd = (float2*)(sm + HS);
#pragma unroll
            for (int i = 0; i < 8; i++) {
                const int m = tid + i * 256;        // float4 index, 0..2047
                const float4 v = __ldcg(src + m);
                const int k   = m >> 2;             // k row of source
                const int b4  = (m & 3) << 2;       // first of 4 bl columns
                hd[(b4 + 0) * PITCH2 + k] = make_float2(v.x, v.x);
                hd[(b4 + 1) * PITCH2 + k] = make_float2(v.y, v.y);
                hd[(b4 + 2) * PITCH2 + k] = make_float2(v.z, v.z);
                hd[(b4 + 3) * PITCH2 + k] = make_float2(v.w, v.w);
            }
        }
        __syncthreads();

        // ---- 4 dot products (2 packed pairs) over k = 0..511 ---------------
        unsigned long long aif0 = 0ull, aif1 = 0ull, aco0 = 0ull, aco1 = 0ull;
#pragma unroll 8
        for (int k = 0; k < DD; k += 4) {
            const ulonglong2 hA = *(const ulonglong2*)(hrow + 2 * k);     // k,k+1
            const ulonglong2 hB = *(const ulonglong2*)(hrow + 2 * k + 4); // k+2,k+3
            const ulonglong2 uA = *(const ulonglong2*)(uifr + 2 * k);
            const ulonglong2 uB = *(const ulonglong2*)(uifr + 2 * k + 4);
            const ulonglong2 vA = *(const ulonglong2*)(ucor + 2 * k);
            const ulonglong2 vB = *(const ulonglong2*)(ucor + 2 * k + 4);
            fma2(aif0, hA.x, uA.x); fma2(aif1, hA.y, uA.y);
            fma2(aif0, hB.x, uB.x); fma2(aif1, hB.y, uB.y);
            fma2(aco0, hA.x, vA.x); fma2(aco1, hA.y, vA.y);
            fma2(aco0, hB.x, vB.x); fma2(aco1, hB.y, vB.y);
        }
        unsigned long long sif, sco;
        asm("add.rn.f32x2 %0, %1, %2;" : "=l"(sif) : "l"(aif0), "l"(aif1));
        asm("add.rn.f32x2 %0, %1, %2;" : "=l"(sco) : "l"(aco0), "l"(aco1));
        float ai, af, ac, ao;
        asm("mov.b64 {%0,%1}, %2;" : "=f"(ai), "=f"(af) : "l"(sif));
        asm("mov.b64 {%0,%1}, %2;" : "=f"(ac), "=f"(ao) : "l"(sco));

        // ---- gates (reference quirks: f uses xi; i has no U-bias) ----------
        const float pi = xi + ai;
        const float pf = xi + af + bfb;
        const float pc = xc + ac + bcb;
        const float po = xo + ao + bob;
        const float ig = 1.f / (1.f + __expf(-pi));
        const float fg = 1.f / (1.f + __expf(-pf));
        const float gg = tanhf(pc);
        const float og = 1.f / (1.f + __expf(-po));
        c = fg * c + ig * gg;
        const float h = og * tanhf(c);

        // ---- publish h, arrive, overlap, wait -------------------------------
        __stcg(&g_h[g][(t + 1) & 1][j][bl], h);
        __syncthreads();
        if (tid == 0) { __threadfence(); gbar_arrive(cnt); }

        const size_t oidx = (size_t)bg * (TT * DD) + (size_t)t * DD + j;
        outH[oidx] = h;
        outC[oidx] = c;
        if (t + 1 < TT) {
            const size_t p2 = (size_t)(t + 1) * (DD * BB) + (size_t)j * BB + bg;
            xi = __ldcg(&g_pre[0][p2]);
            xc = __ldcg(&g_pre[1][p2]);
            xo = __ldcg(&g_pre[2][p2]);
        }

        if (tid == 0) gbar_wait(cnt, (unsigned)(t + 1) * CPG);
        __syncthreads();
    }
}

// ---------------- launch -----------------------------------------------------
extern "C" void kernel_launch(void* const* d_in, const int* in_sizes, int n_in,
                              void* d_out, int out_size) {
    const float* X   = (const float*)d_in[0];
    const float* Wi  = (const float*)d_in[1];
    const float* bi  = (const float*)d_in[2];
    // d_in[3] = Wf, d_in[4] = bf: computed-but-unused in the reference
    const float* Wc  = (const float*)d_in[5];
    const float* bc  = (const float*)d_in[6];
    const float* Wo  = (const float*)d_in[7];
    const float* bo  = (const float*)d_in[8];
    const float* Ui  = (const float*)d_in[9];
    const float* Uf  = (const float*)d_in[10];
    const float* bUf = (const float*)d_in[11];
    const float* Uc  = (const float*)d_in[12];
    const float* bUc = (const float*)d_in[13];
    const float* Uo  = (const float*)d_in[14];
    const float* bUo = (const float*)d_in[15];

    float* outH = (float*)d_out;
    float* outC = outH + (size_t)BB * TT * DD;

    init_kernel<<<128, 256>>>();

    dim3 g1(DD / 128, (BB * TT) / 128, 3);
    gemm_pre_kernel<<<g1, 256>>>(X, Wi, bi, Wc, bc, Wo, bo);

    const size_t smem = (size_t)(3 * JPC * PITCHF) * sizeof(float); // ~193 KB
    cudaFuncSetAttribute(lstm_scan_kernel,
                         cudaFuncAttributeMaxDynamicSharedMemorySize, (int)smem);
    lstm_scan_kernel<<<NG * CPG, 256, smem>>>(Ui, Uf, Uc, Uo, bUf, bUc, bUo,
                                              outH, outC);
}

// round 4
// speedup vs baseline: 3.3499x; 1.1184x over previous
#include <cuda_runtime.h>
#include <cstdint>
#include <cstddef>

#define BB 64
#define TT 512
#define DD 512
#define NG 2          /* batch groups */
#define CPG 64        /* CTAs per group (j split) */
#define BPG 32        /* batch columns per group */
#define JPC 8         /* j rows per CTA */
#define HSTR 548      /* smem row stride (floats): [256][gap 8][256][pad 28] */

// ---------------- scratch ---------------------------------------------------
__device__ float g_pre[3][(size_t)TT * DD * BB];   // [z][t][j][b]
__device__ float g_h[NG][2][BPG][DD];              // [g][buf][b][j]
__device__ unsigned int g_cnt[64];                 // [0] and [32] used

// ---------------- helpers ----------------------------------------------------
__device__ __forceinline__ void fma2(unsigned long long& a,
                                     unsigned long long x, unsigned long long y) {
    asm("fma.rn.f32x2 %0, %1, %2, %0;" : "+l"(a) : "l"(x), "l"(y));
}
__device__ __forceinline__ void cp16(uint32_t dst, const void* src) {
    asm volatile("cp.async.cg.shared.global [%0], [%1], 16;" :: "r"(dst), "l"(src));
}
__device__ __forceinline__ void cp_wait_all() {
    asm volatile("cp.async.commit_group;\n\tcp.async.wait_group 0;" ::: "memory");
}
__device__ __forceinline__ void gbar_arrive(unsigned int* cnt) {
    asm volatile("red.release.gpu.add.u32 [%0], 1;" :: "l"(cnt) : "memory");
}
__device__ __forceinline__ void gbar_wait(unsigned int* cnt, unsigned target) {
    unsigned v;
    do {
        asm volatile("ld.acquire.gpu.u32 %0, [%1];" : "=r"(v) : "l"(cnt) : "memory");
    } while (v < target);
}

// ---------------- Phase 1: Xi/Xc/Xo = X @ W^T + b, output [T][O][B] ----------
// CTA (0,0,0) additionally resets the scan scratch (counters + h buffer 0);
// the scan launches after this kernel completes, so ordering is by stream.
__global__ void __launch_bounds__(256, 2)
gemm_pre_kernel(const float* __restrict__ X,
                const float* __restrict__ Wi, const float* __restrict__ bi,
                const float* __restrict__ Wc, const float* __restrict__ bc,
                const float* __restrict__ Wo, const float* __restrict__ bo)
{
    __shared__ float As[8][128];
    __shared__ float Bs[8][128];

    if (blockIdx.x == 0 && blockIdx.y == 0 && blockIdx.z == 0) {
        if (threadIdx.x < 64) g_cnt[threadIdx.x] = 0u;
        float4* hz = (float4*)&g_h[0][0][0][0];   // zero buffer 0 of both groups
        // g_h[g][0] slices: g=0 at offset 0, g=1 at offset 2*BPG*DD floats
        for (int i = threadIdx.x; i < (BPG * DD) / 4; i += 256) {
            hz[i] = make_float4(0.f, 0.f, 0.f, 0.f);
            hz[i + (2 * BPG * DD) / 4] = make_float4(0.f, 0.f, 0.f, 0.f);
        }
    }

    const int z = blockIdx.z;
    const float* W   = (z == 0) ? Wi : (z == 1) ? Wc : Wo;
    const float* bia = (z == 0) ? bi : (z == 1) ? bc : bo;
    float* out = g_pre[z];

    const int tid = threadIdx.x;
    const int mt = blockIdx.y;
    const int nt = blockIdx.x;

    const int lrow = tid >> 1;
    const int lk4  = (tid & 1) << 2;

    const int m_l = mt * 128 + lrow;     // m = t*64 + b
    const float* Arow = X + ((size_t)(m_l & 63) * TT + (size_t)(m_l >> 6)) * DD;
    const float* Brow = W + (size_t)(nt * 128 + lrow) * DD;

    const int ty = tid >> 4, tx = tid & 15;
    const int m0 = ty * 8, n0 = tx * 8;

    float acc[8][8];
#pragma unroll
    for (int i = 0; i < 8; i++)
#pragma unroll
        for (int jj = 0; jj < 8; jj++) acc[i][jj] = 0.f;

    for (int k0 = 0; k0 < DD; k0 += 8) {
        float4 a4 = *(const float4*)(Arow + k0 + lk4);
        float4 b4 = *(const float4*)(Brow + k0 + lk4);
        As[lk4 + 0][lrow] = a4.x;
        As[lk4 + 1][lrow] = a4.y;
        As[lk4 + 2][lrow] = a4.z;
        As[lk4 + 3][lrow] = a4.w;
        Bs[lk4 + 0][lrow] = b4.x;
        Bs[lk4 + 1][lrow] = b4.y;
        Bs[lk4 + 2][lrow] = b4.z;
        Bs[lk4 + 3][lrow] = b4.w;
        __syncthreads();
#pragma unroll
        for (int kk = 0; kk < 8; kk++) {
            float4 af0 = *(const float4*)&As[kk][m0];
            float4 af1 = *(const float4*)&As[kk][m0 + 4];
            float4 bf0 = *(const float4*)&Bs[kk][n0];
            float4 bf1 = *(const float4*)&Bs[kk][n0 + 4];
            float av[8] = {af0.x, af0.y, af0.z, af0.w, af1.x, af1.y, af1.z, af1.w};
            float bv[8] = {bf0.x, bf0.y, bf0.z, bf0.w, bf1.x, bf1.y, bf1.z, bf1.w};
#pragma unroll
            for (int i = 0; i < 8; i++)
#pragma unroll
                for (int jj = 0; jj < 8; jj++)
                    acc[i][jj] = fmaf(av[i], bv[jj], acc[i][jj]);
        }
        __syncthreads();
    }

    const int mbase = mt * 128 + m0;
    const int tt = mbase >> 6;
    const int b0 = mbase & 63;
#pragma unroll
    for (int jj = 0; jj < 8; jj++) {
        const int o = nt * 128 + n0 + jj;
        const float bz = __ldg(&bia[o]);
        float* op = out + (size_t)tt * (DD * BB) + (size_t)o * BB + b0;
        float4 v0 = make_float4(acc[0][jj] + bz, acc[1][jj] + bz,
                                acc[2][jj] + bz, acc[3][jj] + bz);
        float4 v1 = make_float4(acc[4][jj] + bz, acc[5][jj] + bz,
                                acc[6][jj] + bz, acc[7][jj] + bz);
        *(float4*)op = v0;
        *(float4*)(op + 4) = v1;
    }
}

// ---------------- Phase 2: persistent grouped LSTM scan ---------------------
// 128 CTAs = 64 j-blocks x 2 batch-groups. CTA: 8 j rows x 32 b cols x 4 gates.
// 128 threads: jj = tid>>4 (8), blq = (tid>>1)&7 (8), kh = tid&1 (k half).
// Thread: 4 gates x 4 b (bl = blq + 8l) over its 256-k half; fma2 pairs over k.
// U resident in smem all steps; h staged via cp.async each step; 2-way k
// reduction through smem partials; per-group grid barrier per step.
__global__ void __launch_bounds__(128, 1)
lstm_scan_kernel(const float* __restrict__ Ui, const float* __restrict__ Uf,
                 const float* __restrict__ Uc, const float* __restrict__ Uo,
                 const float* __restrict__ bUf, const float* __restrict__ bUc,
                 const float* __restrict__ bUo,
                 float* __restrict__ outH, float* __restrict__ outC)
{
    extern __shared__ float sm[];
    float* U_s = sm;                    // 32 rows (gate*8+jj) x HSTR
    float* h_s = sm + 32 * HSTR;        // 32 rows (b) x HSTR
    unsigned long long* part = (unsigned long long*)(sm + 64 * HSTR); // 64 slots x 17

    const int tid = threadIdx.x;
    const int jj  = tid >> 4;
    const int blq = (tid >> 1) & 7;
    const int kh  = tid & 1;
    const int g   = blockIdx.x & 1;
    const int j0  = (blockIdx.x >> 1) * JPC;
    const int j   = j0 + jj;
    unsigned int* cnt = &g_cnt[g * 32];

    // Load U once: row = gate*8 + r, col gap at 256.
    for (int idx = tid; idx < 4 * JPC * DD; idx += 128) {
        const int row = idx >> 9;
        const int col = idx & 511;
        const int gate = row >> 3, r = row & 7;
        const float* U = (gate == 0) ? Ui : (gate == 1) ? Uf : (gate == 2) ? Uc : Uo;
        U_s[row * HSTR + col + 8 * (col >> 8)] = __ldg(&U[(size_t)(j0 + r) * DD + col]);
    }

    const float bfb = __ldg(&bUf[j]);
    const float bcb = __ldg(&bUc[j]);
    const float bob = __ldg(&bUo[j]);

    const int koff = kh * 264;     // second half starts after the 8-float gap
    const float* hb0 = h_s + (blq + 0)  * HSTR + koff;
    const float* hb1 = h_s + (blq + 8)  * HSTR + koff;
    const float* hb2 = h_s + (blq + 16) * HSTR + koff;
    const float* hb3 = h_s + (blq + 24) * HSTR + koff;
    const float* u0 = U_s + (0 * 8 + jj) * HSTR + koff;
    const float* u1 = U_s + (1 * 8 + jj) * HSTR + koff;
    const float* u2 = U_s + (2 * 8 + jj) * HSTR + koff;
    const float* u3 = U_s + (3 * 8 + jj) * HSTR + koff;

    float c[4] = {0.f, 0.f, 0.f, 0.f};
    float xi[4], xc[4], xo[4], hv[4];
    if (kh == 0) {
#pragma unroll
        for (int l = 0; l < 4; l++) {
            const int bg = g * BPG + blq + 8 * l;
            xi[l] = __ldcg(&g_pre[0][(size_t)j * BB + bg]);
            xc[l] = __ldcg(&g_pre[1][(size_t)j * BB + bg]);
            xo[l] = __ldcg(&g_pre[2][(size_t)j * BB + bg]);
        }
    }

    for (int t = 0; t < TT; t++) {
        // ---- stage h (64 KB, [b][j] -> smem rows with half-gap) -------------
        {
            const char* src = (const char*)&g_h[g][t & 1][0][0];
#pragma unroll
            for (int i = 0; i < 32; i++) {
                const int m = tid + i * 128;      // float4 id 0..4095
                const int b = m >> 7, k4 = m & 127;
                uint32_t d = (uint32_t)__cvta_generic_to_shared(
                    h_s + b * HSTR + k4 * 4 + 8 * (k4 >> 6));
                cp16(d, src + (size_t)m * 16);
            }
            cp_wait_all();
        }
        __syncthreads();

        // ---- dot products: 16 accs (4 gates x 4 b), fma2 paired over k ------
        unsigned long long a00 = 0, a01 = 0, a02 = 0, a03 = 0;
        unsigned long long a10 = 0, a11 = 0, a12 = 0, a13 = 0;
        unsigned long long a20 = 0, a21 = 0, a22 = 0, a23 = 0;
        unsigned long long a30 = 0, a31 = 0, a32 = 0, a33 = 0;
#pragma unroll 4
        for (int i = 0; i < 64; i++) {
            const int o = 4 * i;
            const ulonglong2 h0 = *(const ulonglong2*)(hb0 + o);
            const ulonglong2 h1 = *(const ulonglong2*)(hb1 + o);
            const ulonglong2 h2 = *(const ulonglong2*)(hb2 + o);
            const ulonglong2 h3 = *(const ulonglong2*)(hb3 + o);
            const ulonglong2 v0 = *(const ulonglong2*)(u0 + o);
            const ulonglong2 v1 = *(const ulonglong2*)(u1 + o);
            const ulonglong2 v2 = *(const ulonglong2*)(u2 + o);
            const ulonglong2 v3 = *(const ulonglong2*)(u3 + o);
            fma2(a00, h0.x, v0.x); fma2(a00, h0.y, v0.y);
            fma2(a01, h1.x, v0.x); fma2(a01, h1.y, v0.y);
            fma2(a02, h2.x, v0.x); fma2(a02, h2.y, v0.y);
            fma2(a03, h3.x, v0.x); fma2(a03, h3.y, v0.y);
            fma2(a10, h0.x, v1.x); fma2(a10, h0.y, v1.y);
            fma2(a11, h1.x, v1.x); fma2(a11, h1.y, v1.y);
            fma2(a12, h2.x, v1.x); fma2(a12, h2.y, v1.y);
            fma2(a13, h3.x, v1.x); fma2(a13, h3.y, v1.y);
            fma2(a20, h0.x, v2.x); fma2(a20, h0.y, v2.y);
            fma2(a21, h1.x, v2.x); fma2(a21, h1.y, v2.y);
            fma2(a22, h2.x, v2.x); fma2(a22, h2.y, v2.y);
            fma2(a23, h3.x, v2.x); fma2(a23, h3.y, v2.y);
            fma2(a30, h0.x, v3.x); fma2(a30, h0.y, v3.y);
            fma2(a31, h1.x, v3.x); fma2(a31, h1.y, v3.y);
            fma2(a32, h2.x, v3.x); fma2(a32, h2.y, v3.y);
            fma2(a33, h3.x, v3.x); fma2(a33, h3.y, v3.y);
        }

        const int slot = (jj * 8 + blq) * 17;
        if (kh) {
            unsigned long long* p = part + slot;
            p[0] = a00; p[1] = a01; p[2]  = a02; p[3]  = a03;
            p[4] = a10; p[5] = a11; p[6]  = a12; p[7]  = a13;
            p[8] = a20; p[9] = a21; p[10] = a22; p[11] = a23;
            p[12] = a30; p[13] = a31; p[14] = a32; p[15] = a33;
        }
        __syncthreads();

        if (!kh) {
            const unsigned long long* p = part + slot;
            unsigned long long m0[16] = {a00, a01, a02, a03, a10, a11, a12, a13,
                                         a20, a21, a22, a23, a30, a31, a32, a33};
            float a[4][4];
#pragma unroll
            for (int q = 0; q < 16; q++) {
                const float2 s = *(const float2*)&m0[q];
                const float2 r = *(const float2*)&p[q];
                a[q >> 2][q & 3] = (s.x + s.y) + (r.x + r.y);
            }
#pragma unroll
            for (int l = 0; l < 4; l++) {
                const int bl = blq + 8 * l;
                const float pi = xi[l] + a[0][l];
                const float pf = xi[l] + a[1][l] + bfb;   // quirk: f uses xi
                const float pc = xc[l] + a[2][l] + bcb;
                const float po = xo[l] + a[3][l] + bob;
                const float ig = 1.f / (1.f + __expf(-pi));
                const float fg = 1.f / (1.f + __expf(-pf));
                const float gg = tanhf(pc);
                const float og = 1.f / (1.f + __expf(-po));
                c[l] = fg * c[l] + ig * gg;
                hv[l] = og * tanhf(c[l]);
                __stcg(&g_h[g][(t + 1) & 1][bl][j], hv[l]);
            }
        }
        __syncthreads();
        if (tid == 0) { __threadfence(); gbar_arrive(cnt); }

        // overlap with the wait: outputs + next-step preactivations
        if (!kh) {
#pragma unroll
            for (int l = 0; l < 4; l++) {
                const int bg = g * BPG + blq + 8 * l;
                const size_t oidx = (size_t)bg * (TT * DD) + (size_t)t * DD + j;
                outH[oidx] = hv[l];
                outC[oidx] = c[l];
            }
            if (t + 1 < TT) {
#pragma unroll
                for (int l = 0; l < 4; l++) {
                    const int bg = g * BPG + blq + 8 * l;
                    const size_t p2 = (size_t)(t + 1) * (DD * BB) + (size_t)j * BB + bg;
                    xi[l] = __ldcg(&g_pre[0][p2]);
                    xc[l] = __ldcg(&g_pre[1][p2]);
                    xo[l] = __ldcg(&g_pre[2][p2]);
                }
            }
        }

        if (tid == 0) gbar_wait(cnt, (unsigned)(t + 1) * CPG);
        __syncthreads();
    }
}

// ---------------- launch -----------------------------------------------------
extern "C" void kernel_launch(void* const* d_in, const int* in_sizes, int n_in,
                              void* d_out, int out_size) {
    const float* X   = (const float*)d_in[0];
    const float* Wi  = (const float*)d_in[1];
    const float* bi  = (const float*)d_in[2];
    // d_in[3] = Wf, d_in[4] = bf: computed-but-unused in the reference
    const float* Wc  = (const float*)d_in[5];
    const float* bc  = (const float*)d_in[6];
    const float* Wo  = (const float*)d_in[7];
    const float* bo  = (const float*)d_in[8];
    const float* Ui  = (const float*)d_in[9];
    const float* Uf  = (const float*)d_in[10];
    const float* bUf = (const float*)d_in[11];
    const float* Uc  = (const float*)d_in[12];
    const float* bUc = (const float*)d_in[13];
    const float* Uo  = (const float*)d_in[14];
    const float* bUo = (const float*)d_in[15];

    float* outH = (float*)d_out;
    float* outC = outH + (size_t)BB * TT * DD;

    dim3 g1(DD / 128, (BB * TT) / 128, 3);
    gemm_pre_kernel<<<g1, 256>>>(X, Wi, bi, Wc, bc, Wo, bo);

    const size_t smem = (size_t)(64 * HSTR) * sizeof(float) + 64 * 17 * 8; // ~146 KB
    cudaFuncSetAttribute(lstm_scan_kernel,
                         cudaFuncAttributeMaxDynamicSharedMemorySize, (int)smem);
    lstm_scan_kernel<<<NG * CPG, 128, smem>>>(Ui, Uf, Uc, Uo, bUf, bUc, bUo,
                                              outH, outC);
}

// round 5
// speedup vs baseline: 3.8065x; 1.1363x over previous
#include <cuda_runtime.h>
#include <cstdint>
#include <cstddef>

#define BB 64
#define TT 512
#define DD 512
#define NG 2          /* batch groups */
#define CPG 64        /* CTAs per group (j split) */
#define BPG 32        /* batch columns per group */
#define JPC 8         /* j rows per CTA */
#define HSTR 528      /* smem row stride (floats), == 16 mod 32 */
#define QOFF 132      /* quarter offset: 128 floats + 4 gap */

// ---------------- scratch ---------------------------------------------------
__device__ float g_pre[3][(size_t)TT * DD * BB];   // [z][t][j][b]
__device__ float g_h[NG][2][BPG][DD];              // [g][buf][b][j]
__device__ unsigned int g_cnt[64];                 // [0] and [32] used

// ---------------- helpers ----------------------------------------------------
__device__ __forceinline__ void fma2(unsigned long long& a,
                                     unsigned long long x, unsigned long long y) {
    asm("fma.rn.f32x2 %0, %1, %2, %0;" : "+l"(a) : "l"(x), "l"(y));
}
__device__ __forceinline__ unsigned long long pack2(float lo, float hi) {
    unsigned long long r;
    asm("mov.b64 %0, {%1,%2};" : "=l"(r) : "f"(lo), "f"(hi));
    return r;
}
__device__ __forceinline__ float fold2(unsigned long long v) {
    float lo, hi;
    asm("mov.b64 {%0,%1}, %2;" : "=f"(lo), "=f"(hi) : "l"(v));
    return lo + hi;
}
__device__ __forceinline__ void cp16(uint32_t dst, const void* src) {
    asm volatile("cp.async.cg.shared.global [%0], [%1], 16;" :: "r"(dst), "l"(src));
}
__device__ __forceinline__ void cp_wait_all() {
    asm volatile("cp.async.commit_group;\n\tcp.async.wait_group 0;" ::: "memory");
}
__device__ __forceinline__ void gbar_arrive(unsigned int* cnt) {
    asm volatile("red.release.gpu.add.u32 [%0], 1;" :: "l"(cnt) : "memory");
}
__device__ __forceinline__ void gbar_wait(unsigned int* cnt, unsigned target) {
    unsigned v;
    do {
        asm volatile("ld.acquire.gpu.u32 %0, [%1];" : "=r"(v) : "l"(cnt) : "memory");
    } while (v < target);
}

// ---------------- Phase 1: Xi/Xc/Xo = X @ W^T + b, output [T][O][B] ----------
// CTA (0,0,0) also resets the scan scratch (counters + h buffer 0).
__global__ void __launch_bounds__(256, 2)
gemm_pre_kernel(const float* __restrict__ X,
                const float* __restrict__ Wi, const float* __restrict__ bi,
                const float* __restrict__ Wc, const float* __restrict__ bc,
                const float* __restrict__ Wo, const float* __restrict__ bo)
{
    __shared__ float As[8][128];
    __shared__ float Bs[8][128];

    if (blockIdx.x == 0 && blockIdx.y == 0 && blockIdx.z == 0) {
        if (threadIdx.x < 64) g_cnt[threadIdx.x] = 0u;
        float4* hz = (float4*)&g_h[0][0][0][0];
        for (int i = threadIdx.x; i < (BPG * DD) / 4; i += 256) {
            hz[i] = make_float4(0.f, 0.f, 0.f, 0.f);
            hz[i + (2 * BPG * DD) / 4] = make_float4(0.f, 0.f, 0.f, 0.f);
        }
    }

    const int z = blockIdx.z;
    const float* W   = (z == 0) ? Wi : (z == 1) ? Wc : Wo;
    const float* bia = (z == 0) ? bi : (z == 1) ? bc : bo;
    float* out = g_pre[z];

    const int tid = threadIdx.x;
    const int mt = blockIdx.y;
    const int nt = blockIdx.x;

    const int lrow = tid >> 1;
    const int lk4  = (tid & 1) << 2;

    const int m_l = mt * 128 + lrow;     // m = t*64 + b
    const float* Arow = X + ((size_t)(m_l & 63) * TT + (size_t)(m_l >> 6)) * DD;
    const float* Brow = W + (size_t)(nt * 128 + lrow) * DD;

    const int ty = tid >> 4, tx = tid & 15;
    const int m0 = ty * 8, n0 = tx * 8;

    unsigned long long acc2[4][8];   // (m-pair) x (8 n), f32x2 over m
#pragma unroll
    for (int i = 0; i < 4; i++)
#pragma unroll
        for (int jj = 0; jj < 8; jj++) acc2[i][jj] = 0ull;

    for (int k0 = 0; k0 < DD; k0 += 8) {
        float4 a4 = *(const float4*)(Arow + k0 + lk4);
        float4 b4 = *(const float4*)(Brow + k0 + lk4);
        As[lk4 + 0][lrow] = a4.x;
        As[lk4 + 1][lrow] = a4.y;
        As[lk4 + 2][lrow] = a4.z;
        As[lk4 + 3][lrow] = a4.w;
        Bs[lk4 + 0][lrow] = b4.x;
        Bs[lk4 + 1][lrow] = b4.y;
        Bs[lk4 + 2][lrow] = b4.z;
        Bs[lk4 + 3][lrow] = b4.w;
        __syncthreads();
#pragma unroll
        for (int kk = 0; kk < 8; kk++) {
            float4 af0 = *(const float4*)&As[kk][m0];
            float4 af1 = *(const float4*)&As[kk][m0 + 4];
            float4 bf0 = *(const float4*)&Bs[kk][n0];
            float4 bf1 = *(const float4*)&Bs[kk][n0 + 4];
            unsigned long long av2[4] = {
                pack2(af0.x, af0.y), pack2(af0.z, af0.w),
                pack2(af1.x, af1.y), pack2(af1.z, af1.w)};
            unsigned long long bd[8] = {
                pack2(bf0.x, bf0.x), pack2(bf0.y, bf0.y),
                pack2(bf0.z, bf0.z), pack2(bf0.w, bf0.w),
                pack2(bf1.x, bf1.x), pack2(bf1.y, bf1.y),
                pack2(bf1.z, bf1.z), pack2(bf1.w, bf1.w)};
#pragma unroll
            for (int ip = 0; ip < 4; ip++)
#pragma unroll
                for (int jj = 0; jj < 8; jj++)
                    fma2(acc2[ip][jj], av2[ip], bd[jj]);
        }
        __syncthreads();
    }

    const int mbase = mt * 128 + m0;
    const int tt = mbase >> 6;
    const int b0 = mbase & 63;
#pragma unroll
    for (int jj = 0; jj < 8; jj++) {
        const int o = nt * 128 + n0 + jj;
        const float bz = __ldg(&bia[o]);
        float* op = out + (size_t)tt * (DD * BB) + (size_t)o * BB + b0;
        const float2 p0 = *(const float2*)&acc2[0][jj];
        const float2 p1 = *(const float2*)&acc2[1][jj];
        const float2 p2 = *(const float2*)&acc2[2][jj];
        const float2 p3 = *(const float2*)&acc2[3][jj];
        float4 v0 = make_float4(p0.x + bz, p0.y + bz, p1.x + bz, p1.y + bz);
        float4 v1 = make_float4(p2.x + bz, p2.y + bz, p3.x + bz, p3.y + bz);
        *(float4*)op = v0;
        *(float4*)(op + 4) = v1;
    }
}

// ---------------- Phase 2: persistent grouped LSTM scan ---------------------
// 128 CTAs = 64 j-blocks x 2 batch-groups, 256 threads (8 warps, 2/SMSP).
// thread = (jj:8, blq:8, kq:4); kq = k quarter (128 k). Each thread: 4 gates x
// 4 b (bl = blq+8l) over its quarter; fma2 pairs adjacent k. k-reduction via
// 2 shfl.xor rounds (kq in low 2 tid bits). U resident in smem; h staged per
// step via cp.async; per-group grid barrier per step.
__global__ void __launch_bounds__(256, 1)
lstm_scan_kernel(const float* __restrict__ Ui, const float* __restrict__ Uf,
                 const float* __restrict__ Uc, const float* __restrict__ Uo,
                 const float* __restrict__ bUf, const float* __restrict__ bUc,
                 const float* __restrict__ bUo,
                 float* __restrict__ outH, float* __restrict__ outC)
{
    extern __shared__ float sm[];
    float* U_s = sm;                    // 32 rows (gate*8+jj) x HSTR
    float* h_s = sm + 32 * HSTR;        // 32 rows (b) x HSTR

    const int tid = threadIdx.x;
    const int kq  = tid & 3;
    const int blq = (tid >> 2) & 7;
    const int jj  = tid >> 5;
    const int g   = blockIdx.x & 1;
    const int j0  = (blockIdx.x >> 1) * JPC;
    const int j   = j0 + jj;
    unsigned int* cnt = &g_cnt[g * 32];

    // Load U once: row = gate*8 + r; columns in 4 gapped quarters.
    for (int idx = tid; idx < 4 * JPC * DD; idx += 256) {
        const int row = idx >> 9;
        const int col = idx & 511;
        const int gate = row >> 3, r = row & 7;
        const float* U = (gate == 0) ? Ui : (gate == 1) ? Uf : (gate == 2) ? Uc : Uo;
        U_s[row * HSTR + (col >> 7) * QOFF + (col & 127)] =
            __ldg(&U[(size_t)(j0 + r) * DD + col]);
    }

    const float bfb = __ldg(&bUf[j]);
    const float bcb = __ldg(&bUc[j]);
    const float bob = __ldg(&bUo[j]);

    const int koff = kq * QOFF;
    const float* hb0 = h_s + (blq + 0)  * HSTR + koff;
    const float* hb1 = h_s + (blq + 8)  * HSTR + koff;
    const float* hb2 = h_s + (blq + 16) * HSTR + koff;
    const float* hb3 = h_s + (blq + 24) * HSTR + koff;
    const float* u0 = U_s + (0 * 8 + jj) * HSTR + koff;
    const float* u1 = U_s + (1 * 8 + jj) * HSTR + koff;
    const float* u2 = U_s + (2 * 8 + jj) * HSTR + koff;
    const float* u3 = U_s + (3 * 8 + jj) * HSTR + koff;

    float c[4] = {0.f, 0.f, 0.f, 0.f};
    float xi[4], xc[4], xo[4], hv[4];
    if (kq == 0) {
#pragma unroll
        for (int l = 0; l < 4; l++) {
            const int bg = g * BPG + blq + 8 * l;
            xi[l] = __ldcg(&g_pre[0][(size_t)j * BB + bg]);
            xc[l] = __ldcg(&g_pre[1][(size_t)j * BB + bg]);
            xo[l] = __ldcg(&g_pre[2][(size_t)j * BB + bg]);
        }
    }

    for (int t = 0; t < TT; t++) {
        // ---- stage h (64 KB) via cp.async into gapped quarters ------------
        {
            const char* src = (const char*)&g_h[g][t & 1][0][0];
#pragma unroll
            for (int i = 0; i < 16; i++) {
                const int m = tid + i * 256;          // float4 id 0..4095
                const int b = m >> 7, k4 = m & 127;
                uint32_t d = (uint32_t)__cvta_generic_to_shared(
                    h_s + b * HSTR + (k4 >> 5) * QOFF + (k4 & 31) * 4);
                cp16(d, src + (size_t)m * 16);
            }
            cp_wait_all();
        }
        __syncthreads();

        // ---- 16 accs (4 gates x 4 b) over my 128-k quarter -----------------
        unsigned long long a[16];
#pragma unroll
        for (int q = 0; q < 16; q++) a[q] = 0ull;
#pragma unroll 4
        for (int i = 0; i < 32; i++) {
            const int o = 4 * i;
            const ulonglong2 h0 = *(const ulonglong2*)(hb0 + o);
            const ulonglong2 h1 = *(const ulonglong2*)(hb1 + o);
            const ulonglong2 h2 = *(const ulonglong2*)(hb2 + o);
            const ulonglong2 h3 = *(const ulonglong2*)(hb3 + o);
            const ulonglong2 v0 = *(const ulonglong2*)(u0 + o);
            const ulonglong2 v1 = *(const ulonglong2*)(u1 + o);
            const ulonglong2 v2 = *(const ulonglong2*)(u2 + o);
            const ulonglong2 v3 = *(const ulonglong2*)(u3 + o);
            fma2(a[0],  h0.x, v0.x); fma2(a[0],  h0.y, v0.y);
            fma2(a[1],  h1.x, v0.x); fma2(a[1],  h1.y, v0.y);
            fma2(a[2],  h2.x, v0.x); fma2(a[2],  h2.y, v0.y);
            fma2(a[3],  h3.x, v0.x); fma2(a[3],  h3.y, v0.y);
            fma2(a[4],  h0.x, v1.x); fma2(a[4],  h0.y, v1.y);
            fma2(a[5],  h1.x, v1.x); fma2(a[5],  h1.y, v1.y);
            fma2(a[6],  h2.x, v1.x); fma2(a[6],  h2.y, v1.y);
            fma2(a[7],  h3.x, v1.x); fma2(a[7],  h3.y, v1.y);
            fma2(a[8],  h0.x, v2.x); fma2(a[8],  h0.y, v2.y);
            fma2(a[9],  h1.x, v2.x); fma2(a[9],  h1.y, v2.y);
            fma2(a[10], h2.x, v2.x); fma2(a[10], h2.y, v2.y);
            fma2(a[11], h3.x, v2.x); fma2(a[11], h3.y, v2.y);
            fma2(a[12], h0.x, v3.x); fma2(a[12], h0.y, v3.y);
            fma2(a[13], h1.x, v3.x); fma2(a[13], h1.y, v3.y);
            fma2(a[14], h2.x, v3.x); fma2(a[14], h2.y, v3.y);
            fma2(a[15], h3.x, v3.x); fma2(a[15], h3.y, v3.y);
        }

        // ---- fold f32x2 -> scalar, butterfly-reduce over kq (lanes ^1, ^2) --
        float s[16];
#pragma unroll
        for (int q = 0; q < 16; q++) s[q] = fold2(a[q]);
#pragma unroll
        for (int q = 0; q < 16; q++) s[q] += __shfl_xor_sync(0xffffffffu, s[q], 1);
#pragma unroll
        for (int q = 0; q < 16; q++) s[q] += __shfl_xor_sync(0xffffffffu, s[q], 2);

        if (kq == 0) {
#pragma unroll
            for (int l = 0; l < 4; l++) {
                const int bl = blq + 8 * l;
                const float pi = xi[l] + s[0 + l];
                const float pf = xi[l] + s[4 + l] + bfb;   // quirk: f uses xi
                const float pc = xc[l] + s[8 + l] + bcb;
                const float po = xo[l] + s[12 + l] + bob;
                const float ig = 1.f / (1.f + __expf(-pi));
                const float fg = 1.f / (1.f + __expf(-pf));
                const float gg = tanhf(pc);
                const float og = 1.f / (1.f + __expf(-po));
                c[l] = fg * c[l] + ig * gg;
                hv[l] = og * tanhf(c[l]);
                __stcg(&g_h[g][(t + 1) & 1][bl][j], hv[l]);
            }
        }
        __syncthreads();
        if (tid == 0) { __threadfence(); gbar_arrive(cnt); }

        // overlap with the wait: outputs + next-step preactivations
        if (kq == 0) {
#pragma unroll
            for (int l = 0; l < 4; l++) {
                const int bg = g * BPG + blq + 8 * l;
                const size_t oidx = (size_t)bg * (TT * DD) + (size_t)t * DD + j;
                outH[oidx] = hv[l];
                outC[oidx] = c[l];
            }
            if (t + 1 < TT) {
#pragma unroll
                for (int l = 0; l < 4; l++) {
                    const int bg = g * BPG + blq + 8 * l;
                    const size_t p2 = (size_t)(t + 1) * (DD * BB) + (size_t)j * BB + bg;
                    xi[l] = __ldcg(&g_pre[0][p2]);
                    xc[l] = __ldcg(&g_pre[1][p2]);
                    xo[l] = __ldcg(&g_pre[2][p2]);
                }
            }
        }

        if (tid == 0) gbar_wait(cnt, (unsigned)(t + 1) * CPG);
        __syncthreads();
    }
}

// ---------------- launch -----------------------------------------------------
extern "C" void kernel_launch(void* const* d_in, const int* in_sizes, int n_in,
                              void* d_out, int out_size) {
    const float* X   = (const float*)d_in[0];
    const float* Wi  = (const float*)d_in[1];
    const float* bi  = (const float*)d_in[2];
    // d_in[3] = Wf, d_in[4] = bf: computed-but-unused in the reference
    const float* Wc  = (const float*)d_in[5];
    const float* bc  = (const float*)d_in[6];
    const float* Wo  = (const float*)d_in[7];
    const float* bo  = (const float*)d_in[8];
    const float* Ui  = (const float*)d_in[9];
    const float* Uf  = (const float*)d_in[10];
    const float* bUf = (const float*)d_in[11];
    const float* Uc  = (const float*)d_in[12];
    const float* bUc = (const float*)d_in[13];
    const float* Uo  = (const float*)d_in[14];
    const float* bUo = (const float*)d_in[15];

    float* outH = (float*)d_out;
    float* outC = outH + (size_t)BB * TT * DD;

    dim3 g1(DD / 128, (BB * TT) / 128, 3);
    gemm_pre_kernel<<<g1, 256>>>(X, Wi, bi, Wc, bc, Wo, bo);

    const size_t smem = (size_t)(64 * HSTR) * sizeof(float); // 132 KB
    cudaFuncSetAttribute(lstm_scan_kernel,
                         cudaFuncAttributeMaxDynamicSharedMemorySize, (int)smem);
    lstm_scan_kernel<<<NG * CPG, 256, smem>>>(Ui, Uf, Uc, Uo, bUf, bUc, bUo,
                                              outH, outC);
}

// round 6
// speedup vs baseline: 5.2002x; 1.3662x over previous
#include <cuda_runtime.h>
#include <cuda_bf16.h>
#include <cstdint>
#include <cstddef>

#define BB 64
#define TT 512
#define DD 512
#define NG 2          /* batch groups */
#define CPG 64        /* CTAs per group (j split) */
#define BPG 32        /* batch columns per group */
#define JPC 8         /* j rows per CTA */

#define RSTRB 1040    /* bf16 tile row stride bytes (520 bf16): LDSM conflict-free */
#define OFF_U1 0
#define OFF_U2 33280
#define OFF_H1 66560
#define OFF_H2 99840
#define OFF_P  133120 /* fp32 partials [4][32][34] = 17408 B */
#define OFF_HO 150528 /* fp32 [32][9] */
#define OFF_CO 151680
#define SMEM_SCAN 152832

// ---------------- scratch ---------------------------------------------------
__device__ float g_pre[3][(size_t)TT * DD * BB];          // [z][t][j][b]
__device__ unsigned short g_hs[NG][2][2][BPG][DD];        // h split: [g][buf][s][b][k] bf16
__device__ unsigned int g_cnt[64];                        // [0], [32]

// ---------------- helpers ----------------------------------------------------
__device__ __forceinline__ void fma2(unsigned long long& a,
                                     unsigned long long x, unsigned long long y) {
    asm("fma.rn.f32x2 %0, %1, %2, %0;" : "+l"(a) : "l"(x), "l"(y));
}
__device__ __forceinline__ unsigned long long pack2(float lo, float hi) {
    unsigned long long r;
    asm("mov.b64 %0, {%1,%2};" : "=l"(r) : "f"(lo), "f"(hi));
    return r;
}
__device__ __forceinline__ void cp16(uint32_t dst, const void* src) {
    asm volatile("cp.async.cg.shared.global [%0], [%1], 16;" :: "r"(dst), "l"(src));
}
__device__ __forceinline__ void cp_wait_all() {
    asm volatile("cp.async.commit_group;\n\tcp.async.wait_group 0;" ::: "memory");
}
__device__ __forceinline__ void gbar_arrive(unsigned int* cnt) {
    asm volatile("red.release.gpu.add.u32 [%0], 1;" :: "l"(cnt) : "memory");
}
__device__ __forceinline__ void gbar_wait(unsigned int* cnt, unsigned target) {
    unsigned v;
    do {
        asm volatile("ld.acquire.gpu.u32 %0, [%1];" : "=r"(v) : "l"(cnt) : "memory");
    } while (v < target);
}
__device__ __forceinline__ void ldsm_x4(uint32_t* r, uint32_t addr) {
    asm volatile("ldmatrix.sync.aligned.m8n8.x4.shared.b16 {%0,%1,%2,%3}, [%4];"
                 : "=r"(r[0]), "=r"(r[1]), "=r"(r[2]), "=r"(r[3]) : "r"(addr));
}
__device__ __forceinline__ void ldsm_x2(uint32_t* r, uint32_t addr) {
    asm volatile("ldmatrix.sync.aligned.m8n8.x2.shared.b16 {%0,%1}, [%2];"
                 : "=r"(r[0]), "=r"(r[1]) : "r"(addr));
}
__device__ __forceinline__ void mma_bf16(float* d, const uint32_t* a, const uint32_t* b) {
    asm volatile(
        "mma.sync.aligned.m16n8k16.row.col.f32.bf16.bf16.f32 "
        "{%0,%1,%2,%3},{%4,%5,%6,%7},{%8,%9},{%0,%1,%2,%3};"
        : "+f"(d[0]), "+f"(d[1]), "+f"(d[2]), "+f"(d[3])
        : "r"(a[0]), "r"(a[1]), "r"(a[2]), "r"(a[3]), "r"(b[0]), "r"(b[1]));
}

// ---------------- Phase 1: Xi/Xc/Xo = X @ W^T + b, output [T][O][B] ----------
// CTA (0,0,0) also resets scan scratch (counters + h split buffers).
__global__ void __launch_bounds__(256, 2)
gemm_pre_kernel(const float* __restrict__ X,
                const float* __restrict__ Wi, const float* __restrict__ bi,
                const float* __restrict__ Wc, const float* __restrict__ bc,
                const float* __restrict__ Wo, const float* __restrict__ bo)
{
    __shared__ float As[8][128];
    __shared__ float Bs[8][128];

    if (blockIdx.x == 0 && blockIdx.y == 0 && blockIdx.z == 0) {
        if (threadIdx.x < 64) g_cnt[threadIdx.x] = 0u;
        uint4* hz = (uint4*)g_hs;   // zero entire split-h array (256 KB)
        const int nchunks = (int)(sizeof(g_hs) / 16);
        for (int i = threadIdx.x; i < nchunks; i += 256)
            hz[i] = make_uint4(0u, 0u, 0u, 0u);
    }

    const int z = blockIdx.z;
    const float* W   = (z == 0) ? Wi : (z == 1) ? Wc : Wo;
    const float* bia = (z == 0) ? bi : (z == 1) ? bc : bo;
    float* out = g_pre[z];

    const int tid = threadIdx.x;
    const int mt = blockIdx.y;
    const int nt = blockIdx.x;

    const int lrow = tid >> 1;
    const int lk4  = (tid & 1) << 2;

    const int m_l = mt * 128 + lrow;     // m = t*64 + b
    const float* Arow = X + ((size_t)(m_l & 63) * TT + (size_t)(m_l >> 6)) * DD;
    const float* Brow = W + (size_t)(nt * 128 + lrow) * DD;

    const int ty = tid >> 4, tx = tid & 15;
    const int m0 = ty * 8, n0 = tx * 8;

    unsigned long long acc2[4][8];
#pragma unroll
    for (int i = 0; i < 4; i++)
#pragma unroll
        for (int jj = 0; jj < 8; jj++) acc2[i][jj] = 0ull;

    for (int k0 = 0; k0 < DD; k0 += 8) {
        float4 a4 = *(const float4*)(Arow + k0 + lk4);
        float4 b4 = *(const float4*)(Brow + k0 + lk4);
        As[lk4 + 0][lrow] = a4.x;
        As[lk4 + 1][lrow] = a4.y;
        As[lk4 + 2][lrow] = a4.z;
        As[lk4 + 3][lrow] = a4.w;
        Bs[lk4 + 0][lrow] = b4.x;
        Bs[lk4 + 1][lrow] = b4.y;
        Bs[lk4 + 2][lrow] = b4.z;
        Bs[lk4 + 3][lrow] = b4.w;
        __syncthreads();
#pragma unroll
        for (int kk = 0; kk < 8; kk++) {
            float4 af0 = *(const float4*)&As[kk][m0];
            float4 af1 = *(const float4*)&As[kk][m0 + 4];
            float4 bf0 = *(const float4*)&Bs[kk][n0];
            float4 bf1 = *(const float4*)&Bs[kk][n0 + 4];
            unsigned long long av2[4] = {
                pack2(af0.x, af0.y), pack2(af0.z, af0.w),
                pack2(af1.x, af1.y), pack2(af1.z, af1.w)};
            unsigned long long bd[8] = {
                pack2(bf0.x, bf0.x), pack2(bf0.y, bf0.y),
                pack2(bf0.z, bf0.z), pack2(bf0.w, bf0.w),
                pack2(bf1.x, bf1.x), pack2(bf1.y, bf1.y),
                pack2(bf1.z, bf1.z), pack2(bf1.w, bf1.w)};
#pragma unroll
            for (int ip = 0; ip < 4; ip++)
#pragma unroll
                for (int jj = 0; jj < 8; jj++)
                    fma2(acc2[ip][jj], av2[ip], bd[jj]);
        }
        __syncthreads();
    }

    const int mbase = mt * 128 + m0;
    const int tt = mbase >> 6;
    const int b0 = mbase & 63;
#pragma unroll
    for (int jj = 0; jj < 8; jj++) {
        const int o = nt * 128 + n0 + jj;
        const float bz = __ldg(&bia[o]);
        float* op = out + (size_t)tt * (DD * BB) + (size_t)o * BB + b0;
        const float2 p0 = *(const float2*)&acc2[0][jj];
        const float2 p1 = *(const float2*)&acc2[1][jj];
        const float2 p2 = *(const float2*)&acc2[2][jj];
        const float2 p3 = *(const float2*)&acc2[3][jj];
        *(float4*)op = make_float4(p0.x + bz, p0.y + bz, p1.x + bz, p1.y + bz);
        *(float4*)(op + 4) = make_float4(p2.x + bz, p2.y + bz, p3.x + bz, p3.y + bz);
    }
}

// ---------------- Phase 2: tensor-core persistent LSTM scan ------------------
// 128 CTAs = 64 j-blocks x 2 batch-groups, 256 threads (8 warps).
// Recurrent GEMM per CTA per step: [m=32 b] x [n=32 jg] x [k=512] via
// mma.sync m16n8k16 bf16 with 2-way bf16 splits of h and U (4 cross terms,
// fp32 accumulate -> fp32-grade accuracy). U fragments (both splits) live in
// registers for ALL steps. Warp = (kw: k-slice of 128, nh: n-half of 16).
// h exchanged through global as pre-split bf16 pairs; k-reduction via smem.
__global__ void __launch_bounds__(256, 1)
lstm_scan_kernel(const float* __restrict__ Ui, const float* __restrict__ Uf,
                 const float* __restrict__ Uc, const float* __restrict__ Uo,
                 const float* __restrict__ bUf, const float* __restrict__ bUc,
                 const float* __restrict__ bUo,
                 float* __restrict__ outH, float* __restrict__ outC)
{
    extern __shared__ char smem[];
    const uint32_t sbase = (uint32_t)__cvta_generic_to_shared(smem);

    const int tid  = threadIdx.x;
    const int lane = tid & 31;
    const int warp = tid >> 5;
    const int kw = warp & 3;          // k slice: [kw*128, kw*128+128)
    const int nh = warp >> 2;         // n half: [nh*16, nh*16+16)
    const int g  = blockIdx.x & 1;
    const int j0 = (blockIdx.x >> 1) * JPC;
    unsigned int* cnt = &g_cnt[g * 32];

    // ---- load U tile, split into bf16 hi/lo smem tiles ----------------------
    for (int idx = tid; idx < 32 * DD; idx += 256) {
        const int n = idx >> 9, k = idx & 511;     // n = gate*8 + jl
        const int gate = n >> 3, jl = n & 7;
        const float* U = (gate == 0) ? Ui : (gate == 1) ? Uf : (gate == 2) ? Uc : Uo;
        const float v = __ldg(&U[(size_t)(j0 + jl) * DD + k]);
        const __nv_bfloat16 hi = __float2bfloat16(v);
        const __nv_bfloat16 lo = __float2bfloat16(v - __bfloat162float(hi));
        *(__nv_bfloat16*)(smem + OFF_U1 + n * RSTRB + k * 2) = hi;
        *(__nv_bfloat16*)(smem + OFF_U2 + n * RSTRB + k * 2) = lo;
    }
    __syncthreads();

    // ---- B fragments in registers, kept for all 512 steps -------------------
    uint32_t bc1[2][8][2], bc2[2][8][2];
    {
        const int brow = lane & 7;
        const int bsel = (lane >> 3) & 1;    // 0: k+0..7 matrix, 1: k+8..15
#pragma unroll
        for (int nt = 0; nt < 2; nt++) {
            const int n0 = nh * 16 + nt * 8;
#pragma unroll
            for (int kt = 0; kt < 8; kt++) {
                const int k0 = kw * 128 + kt * 16;
                const uint32_t boff = (uint32_t)((n0 + brow) * RSTRB + (k0 + bsel * 8) * 2);
                ldsm_x2(bc1[nt][kt], sbase + OFF_U1 + boff);
                ldsm_x2(bc2[nt][kt], sbase + OFF_U2 + boff);
            }
        }
    }

    // ---- A-fragment lane offset (within h tiles) ----------------------------
    const int rA = (lane & 7) + ((lane >> 3) & 1) * 8;
    const int cA = (lane >> 4) * 8;
    const uint32_t aoff = (uint32_t)(rA * RSTRB + (kw * 128 + cA) * 2);

    // ---- gate-thread identity: (jg = warp, bb = lane) ------------------------
    const int jg = warp;                 // 0..7
    const int bb = lane;                 // 0..31
    const int jglob = j0 + jg;
    const int bglob = g * BPG + bb;
    const float bfb = __ldg(&bUf[jglob]);
    const float bcb = __ldg(&bUc[jglob]);
    const float bob = __ldg(&bUo[jglob]);

    float c = 0.f;
    float xi = __ldcg(&g_pre[0][(size_t)jglob * BB + bglob]);
    float xc = __ldcg(&g_pre[1][(size_t)jglob * BB + bglob]);
    float xo = __ldcg(&g_pre[2][(size_t)jglob * BB + bglob]);

    float* P  = (float*)(smem + OFF_P);
    float* HO = (float*)(smem + OFF_HO);
    float* CO = (float*)(smem + OFF_CO);

    for (int t = 0; t < TT; t++) {
        // ---- stage h splits (64 KB) into padded bf16 smem tiles -------------
        {
            const char* src = (const char*)&g_hs[g][t & 1][0][0][0];
#pragma unroll
            for (int i = 0; i < 16; i++) {
                const int m = tid + i * 256;       // 16B chunk id 0..4095
                const int s  = m >> 11;
                const int cc = m & 2047;
                const int b  = cc >> 6, kc = cc & 63;
                const uint32_t dst = sbase + (s ? OFF_H2 : OFF_H1) + b * RSTRB + kc * 16;
                cp16(dst, src + (size_t)s * (BPG * DD * 2) + b * (DD * 2) + kc * 16);
            }
            cp_wait_all();
        }
        __syncthreads();

        // ---- MMA: acc += h1*U1 + h2*U1 + h1*U2 + h2*U2 ----------------------
        float acc[2][2][4] = {};
#pragma unroll
        for (int mt = 0; mt < 2; mt++) {
#pragma unroll
            for (int kt = 0; kt < 8; kt++) {
                uint32_t a1[4], a2[4];
                const uint32_t ao = mt * (16 * RSTRB) + kt * 32 + aoff;
                ldsm_x4(a1, sbase + OFF_H1 + ao);
                ldsm_x4(a2, sbase + OFF_H2 + ao);
#pragma unroll
                for (int nt = 0; nt < 2; nt++) {
                    mma_bf16(acc[mt][nt], a1, bc1[nt][kt]);
                    mma_bf16(acc[mt][nt], a2, bc1[nt][kt]);
                    mma_bf16(acc[mt][nt], a1, bc2[nt][kt]);
                    mma_bf16(acc[mt][nt], a2, bc2[nt][kt]);
                }
            }
        }

        // ---- k-partials to smem ---------------------------------------------
        {
            const int gq = lane >> 2, t2 = lane & 3;
#pragma unroll
            for (int mt = 0; mt < 2; mt++)
#pragma unroll
                for (int nt = 0; nt < 2; nt++) {
                    const int n0 = nh * 16 + nt * 8 + t2 * 2;
                    const int m0 = mt * 16 + gq;
                    *(float2*)&P[(kw * 32 + m0) * 34 + n0] =
                        make_float2(acc[mt][nt][0], acc[mt][nt][1]);
                    *(float2*)&P[(kw * 32 + m0 + 8) * 34 + n0] =
                        make_float2(acc[mt][nt][2], acc[mt][nt][3]);
                }
        }
        __syncthreads();

        // ---- gates (quirks: f uses xi; i has no U-bias) ----------------------
        float h;
        {
            float pre[4];
#pragma unroll
            for (int ga = 0; ga < 4; ga++) {
                const int n = ga * 8 + jg;
                pre[ga] = (P[(0 * 32 + bb) * 34 + n] + P[(1 * 32 + bb) * 34 + n]) +
                          (P[(2 * 32 + bb) * 34 + n] + P[(3 * 32 + bb) * 34 + n]);
            }
            const float pi = xi + pre[0];
            const float pf = xi + pre[1] + bfb;
            const float pc = xc + pre[2] + bcb;
            const float po = xo + pre[3] + bob;
            const float ig = 1.f / (1.f + __expf(-pi));
            const float fg = 1.f / (1.f + __expf(-pf));
            const float gg = tanhf(pc);
            const float og = 1.f / (1.f + __expf(-po));
            c = fg * c + ig * gg;
            h = og * tanhf(c);

            // publish split h for next step
            const __nv_bfloat16 h1 = __float2bfloat16(h);
            const __nv_bfloat16 h2 = __float2bfloat16(h - __bfloat162float(h1));
            g_hs[g][(t + 1) & 1][0][bb][jglob] = *(const unsigned short*)&h1;
            g_hs[g][(t + 1) & 1][1][bb][jglob] = *(const unsigned short*)&h2;

            HO[bb * 9 + jg] = h;
            CO[bb * 9 + jg] = c;
        }
        __syncthreads();
        if (tid == 0) { __threadfence(); gbar_arrive(cnt); }

        // ---- overlap with barrier wait: coalesced outputs + next-x preload ---
        {
            const int m = tid & 127;
            const int ob = m >> 2, oj = (m & 3) * 2;
            const size_t obase = (size_t)(g * BPG + ob) * (TT * DD) +
                                 (size_t)t * DD + j0 + oj;
            const float* S = (tid < 128) ? HO : CO;
            float* O = (tid < 128) ? outH : outC;
            *(float2*)&O[obase] = make_float2(S[ob * 9 + oj], S[ob * 9 + oj + 1]);
        }
        if (t + 1 < TT) {
            const size_t p2 = (size_t)(t + 1) * (DD * BB) + (size_t)jglob * BB + bglob;
            xi = __ldcg(&g_pre[0][p2]);
            xc = __ldcg(&g_pre[1][p2]);
            xo = __ldcg(&g_pre[2][p2]);
        }

        if (tid == 0) gbar_wait(cnt, (unsigned)(t + 1) * CPG);
        __syncthreads();
    }
}

// ---------------- launch -----------------------------------------------------
extern "C" void kernel_launch(void* const* d_in, const int* in_sizes, int n_in,
                              void* d_out, int out_size) {
    const float* X   = (const float*)d_in[0];
    const float* Wi  = (const float*)d_in[1];
    const float* bi  = (const float*)d_in[2];
    // d_in[3] = Wf, d_in[4] = bf: computed-but-unused in the reference
    const float* Wc  = (const float*)d_in[5];
    const float* bc  = (const float*)d_in[6];
    const float* Wo  = (const float*)d_in[7];
    const float* bo  = (const float*)d_in[8];
    const float* Ui  = (const float*)d_in[9];
    const float* Uf  = (const float*)d_in[10];
    const float* bUf = (const float*)d_in[11];
    const float* Uc  = (const float*)d_in[12];
    const float* bUc = (const float*)d_in[13];
    const float* Uo  = (const float*)d_in[14];
    const float* bUo = (const float*)d_in[15];

    float* outH = (float*)d_out;
    float* outC = outH + (size_t)BB * TT * DD;

    dim3 g1(DD / 128, (BB * TT) / 128, 3);
    gemm_pre_kernel<<<g1, 256>>>(X, Wi, bi, Wc, bc, Wo, bo);

    cudaFuncSetAttribute(lstm_scan_kernel,
                         cudaFuncAttributeMaxDynamicSharedMemorySize, SMEM_SCAN);
    lstm_scan_kernel<<<NG * CPG, 256, SMEM_SCAN>>>(Ui, Uf, Uc, Uo, bUf, bUc, bUo,
                                                   outH, outC);
}

// round 7
// speedup vs baseline: 6.5415x; 1.2579x over previous
#include <cuda_runtime.h>
#include <cuda_bf16.h>
#include <cstdint>
#include <cstddef>

#define BB 64
#define TT 512
#define DD 512
#define NG 2          /* batch groups */
#define CPG 64        /* CTAs per group (j split) */
#define BPG 32        /* batch columns per group */
#define JPC 8         /* j rows per CTA */

#define RSTRB 1040    /* scan bf16 tile row stride bytes */
#define OFF_U1 0
#define OFF_U2 33280
#define OFF_H1 66560
#define OFF_H2 99840
#define OFF_P  133120
#define OFF_HO 150528
#define OFF_CO 151680
#define SMEM_SCAN 152832

/* phase-1 tensor GEMM tiles */
#define GSTR 80        /* smem row stride bytes (40 bf16) */
#define GARR 10240     /* one 128x32 bf16 tile (padded) */
#define SMEM_GEMM 81920

// ---------------- scratch ---------------------------------------------------
__device__ float g_pre[3][(size_t)TT * DD * BB];          // [z][t][j][b]
__device__ unsigned short g_hs[NG][2][2][BPG][DD];        // h split bf16
__device__ unsigned int g_cnt[64];
__device__ __nv_bfloat16 g_Xs[2][(size_t)BB * TT * DD];   // X splits [m=t*64+b][k]
__device__ __nv_bfloat16 g_Ws[3][2][DD * DD];             // W splits [z][s][n][k]

// ---------------- helpers ----------------------------------------------------
__device__ __forceinline__ void cp16(uint32_t dst, const void* src) {
    asm volatile("cp.async.cg.shared.global [%0], [%1], 16;" :: "r"(dst), "l"(src));
}
__device__ __forceinline__ void cp_commit() {
    asm volatile("cp.async.commit_group;" ::: "memory");
}
__device__ __forceinline__ void cp_wait_all() {
    asm volatile("cp.async.commit_group;\n\tcp.async.wait_group 0;" ::: "memory");
}
template <int N> __device__ __forceinline__ void cp_wait() {
    asm volatile("cp.async.wait_group %0;" :: "n"(N) : "memory");
}
__device__ __forceinline__ void gbar_arrive(unsigned int* cnt) {
    asm volatile("red.release.gpu.add.u32 [%0], 1;" :: "l"(cnt) : "memory");
}
__device__ __forceinline__ void gbar_wait(unsigned int* cnt, unsigned target) {
    unsigned v;
    do {
        asm volatile("ld.acquire.gpu.u32 %0, [%1];" : "=r"(v) : "l"(cnt) : "memory");
    } while (v < target);
}
__device__ __forceinline__ void ldsm_x4(uint32_t* r, uint32_t addr) {
    asm volatile("ldmatrix.sync.aligned.m8n8.x4.shared.b16 {%0,%1,%2,%3}, [%4];"
                 : "=r"(r[0]), "=r"(r[1]), "=r"(r[2]), "=r"(r[3]) : "r"(addr));
}
__device__ __forceinline__ void ldsm_x2(uint32_t* r, uint32_t addr) {
    asm volatile("ldmatrix.sync.aligned.m8n8.x2.shared.b16 {%0,%1}, [%2];"
                 : "=r"(r[0]), "=r"(r[1]) : "r"(addr));
}
__device__ __forceinline__ void mma_bf16(float* d, const uint32_t* a, const uint32_t* b) {
    asm volatile(
        "mma.sync.aligned.m16n8k16.row.col.f32.bf16.bf16.f32 "
        "{%0,%1,%2,%3},{%4,%5,%6,%7},{%8,%9},{%0,%1,%2,%3};"
        : "+f"(d[0]), "+f"(d[1]), "+f"(d[2]), "+f"(d[3])
        : "r"(a[0]), "r"(a[1]), "r"(a[2]), "r"(a[3]), "r"(b[0]), "r"(b[1]));
}
__device__ __forceinline__ uint2 split4(float4 v, uint2& lo) {
    __nv_bfloat16 h0 = __float2bfloat16(v.x), h1 = __float2bfloat16(v.y);
    __nv_bfloat16 h2 = __float2bfloat16(v.z), h3 = __float2bfloat16(v.w);
    __nv_bfloat16 l0 = __float2bfloat16(v.x - __bfloat162float(h0));
    __nv_bfloat16 l1 = __float2bfloat16(v.y - __bfloat162float(h1));
    __nv_bfloat16 l2 = __float2bfloat16(v.z - __bfloat162float(h2));
    __nv_bfloat16 l3 = __float2bfloat16(v.w - __bfloat162float(h3));
    __nv_bfloat162 hp0{h0, h1}, hp1{h2, h3}, lp0{l0, l1}, lp1{l2, l3};
    uint2 hi;
    hi.x = *(unsigned*)&hp0; hi.y = *(unsigned*)&hp1;
    lo.x = *(unsigned*)&lp0; lo.y = *(unsigned*)&lp1;
    return hi;
}

// ---------------- Phase 0: split X/W into bf16 hi/lo, init scan state --------
__global__ void __launch_bounds__(256)
split_kernel(const float* __restrict__ X, const float* __restrict__ Wi,
             const float* __restrict__ Wc, const float* __restrict__ Wo)
{
    const int i = blockIdx.x * 256 + threadIdx.x;
    // X: [b][t][k] -> rows m = t*64 + b
    if (i < BB * TT * (DD / 4)) {
        const int m = i >> 7, k4 = i & 127;
        const int b = m & 63, t = m >> 6;
        const float4 v = __ldg((const float4*)X + ((size_t)b * TT + t) * 128 + k4);
        uint2 lo;
        const uint2 hi = split4(v, lo);
        *(uint2*)&g_Xs[0][(size_t)m * DD + k4 * 4] = hi;
        *(uint2*)&g_Xs[1][(size_t)m * DD + k4 * 4] = lo;
    }
    // W: 3 gates x [n][k]
    if (i < 3 * DD * (DD / 4)) {
        const int z = i / (DD * 128);
        const int r = i - z * (DD * 128);
        const int n = r >> 7, k4 = r & 127;
        const float* W = (z == 0) ? Wi : (z == 1) ? Wc : Wo;
        const float4 v = __ldg((const float4*)W + (size_t)n * 128 + k4);
        uint2 lo;
        const uint2 hi = split4(v, lo);
        *(uint2*)&g_Ws[z][0][(size_t)n * DD + k4 * 4] = hi;
        *(uint2*)&g_Ws[z][1][(size_t)n * DD + k4 * 4] = lo;
    }
    // scan state init
    if (i < 64) g_cnt[i] = 0u;
    if (i < (int)(sizeof(g_hs) / 16))
        ((uint4*)g_hs)[i] = make_uint4(0u, 0u, 0u, 0u);
}

// ---------------- Phase 1: tensor-core GEMM, out [T][O][B] + bias ------------
// grid (4 n-tiles, 256 m-tiles, 3 gates), 256 threads. CTA tile 128x128, K=512
// staged k=32 double-buffered via cp.async. bf16 2-split, 3 cross products.
__global__ void __launch_bounds__(256)
gemm_tc_kernel(const float* __restrict__ bi, const float* __restrict__ bc,
               const float* __restrict__ bo)
{
    extern __shared__ char smem[];
    const uint32_t sbase = (uint32_t)__cvta_generic_to_shared(smem);

    const int tid  = threadIdx.x;
    const int lane = tid & 31;
    const int warp = tid >> 5;
    const int wm = warp >> 1, wn = warp & 1;
    const int ntile = blockIdx.x, mt = blockIdx.y, z = blockIdx.z;
    const float* bia = (z == 0) ? bi : (z == 1) ? bc : bo;

    // stage one k=32 slab (A hi/lo + B hi/lo) into buffer s
    auto stage = [&](int s, int kt) {
        const int k0 = kt * 32;
#pragma unroll
        for (int j = 0; j < 8; j++) {
            const int idx = tid + j * 256;          // 0..2047
            const int arr = idx >> 9;               // 0:A1 1:A2 2:B1 3:B2
            const int r   = (idx >> 2) & 127;
            const int ch  = idx & 3;
            const uint32_t dst = sbase + (uint32_t)((arr * 2 + s) * GARR + r * GSTR + ch * 16);
            const __nv_bfloat16* src;
            if (arr < 2)
                src = &g_Xs[arr][(size_t)(mt * 128 + r) * DD + k0 + ch * 8];
            else
                src = &g_Ws[z][arr - 2][(size_t)(ntile * 128 + r) * DD + k0 + ch * 8];
            cp16(dst, src);
        }
    };

    float acc[2][8][4] = {};

    stage(0, 0); cp_commit();
    stage(1, 1); cp_commit();
    cp_wait<1>();
    __syncthreads();

    // ldsm lane offsets
    const int rA = (lane & 7) + ((lane >> 3) & 1) * 8;
    const int cA = (lane >> 4) * 8;
    const int rB = (lane & 7) + ((lane >> 4) << 3);
    const int cB = ((lane >> 3) & 1) * 8;

    for (int kt = 0; kt < 16; kt++) {
        const int cur = kt & 1;
        const uint32_t A1 = sbase + (0 * 2 + cur) * GARR;
        const uint32_t A2 = sbase + (1 * 2 + cur) * GARR;
        const uint32_t B1 = sbase + (2 * 2 + cur) * GARR;
        const uint32_t B2 = sbase + (3 * 2 + cur) * GARR;

#pragma unroll
        for (int k16 = 0; k16 < 2; k16++) {
            uint32_t a1[2][4], a2[2][4], b1[8][2], b2[8][2];
#pragma unroll
            for (int m2 = 0; m2 < 2; m2++) {
                const uint32_t ao =
                    (uint32_t)((wm * 32 + m2 * 16 + rA) * GSTR + (k16 * 16 + cA) * 2);
                ldsm_x4(a1[m2], A1 + ao);
                ldsm_x4(a2[m2], A2 + ao);
            }
#pragma unroll
            for (int n16 = 0; n16 < 4; n16++) {
                const uint32_t bo_ =
                    (uint32_t)((wn * 64 + n16 * 16 + rB) * GSTR + (k16 * 16 + cB) * 2);
                uint32_t r1[4], r2[4];
                ldsm_x4(r1, B1 + bo_);
                ldsm_x4(r2, B2 + bo_);
                b1[n16 * 2][0] = r1[0]; b1[n16 * 2][1] = r1[1];
                b1[n16 * 2 + 1][0] = r1[2]; b1[n16 * 2 + 1][1] = r1[3];
                b2[n16 * 2][0] = r2[0]; b2[n16 * 2][1] = r2[1];
                b2[n16 * 2 + 1][0] = r2[2]; b2[n16 * 2 + 1][1] = r2[3];
            }
            // 3 cross products (hi*hi, hi*lo, lo*hi); acc reuse distance 16
#pragma unroll
            for (int m2 = 0; m2 < 2; m2++)
#pragma unroll
                for (int n8 = 0; n8 < 8; n8++) mma_bf16(acc[m2][n8], a1[m2], b1[n8]);
#pragma unroll
            for (int m2 = 0; m2 < 2; m2++)
#pragma unroll
                for (int n8 = 0; n8 < 8; n8++) mma_bf16(acc[m2][n8], a1[m2], b2[n8]);
#pragma unroll
            for (int m2 = 0; m2 < 2; m2++)
#pragma unroll
                for (int n8 = 0; n8 < 8; n8++) mma_bf16(acc[m2][n8], a2[m2], b1[n8]);
        }

        if (kt == 15) break;
        __syncthreads();
        if (kt + 2 < 16) { stage(cur, kt + 2); cp_commit(); cp_wait<1>(); }
        else             { cp_wait<0>(); }
        __syncthreads();
    }

    // ---- epilogue: transpose via smem -> [t][o][b] + bias --------------------
    __syncthreads();
    float* ep = (float*)smem;          // [n=128][m pad 132]
    {
        const int gq = lane >> 2, c2 = (lane & 3) * 2;
#pragma unroll
        for (int m2 = 0; m2 < 2; m2++)
#pragma unroll
            for (int n8 = 0; n8 < 8; n8++) {
                const int m = wm * 32 + m2 * 16 + gq;
                const int n = wn * 64 + n8 * 8 + c2;
                ep[n * 132 + m]           = acc[m2][n8][0];
                ep[(n + 1) * 132 + m]     = acc[m2][n8][1];
                ep[n * 132 + m + 8]       = acc[m2][n8][2];
                ep[(n + 1) * 132 + m + 8] = acc[m2][n8][3];
            }
    }
    __syncthreads();
    {
        float* out = g_pre[z];
        const int t0 = mt * 2;
#pragma unroll
        for (int i = 0; i < 16; i++) {
            const int idx = tid + i * 256;      // 0..4095
            const int o = idx >> 5;
            const int tloc = (idx >> 4) & 1;
            const int b4 = (idx & 15) * 4;
            const float4 v = *(const float4*)&ep[o * 132 + tloc * 64 + b4];
            const float bz = __ldg(&bia[ntile * 128 + o]);
            float* op = out + (size_t)(t0 + tloc) * (DD * BB) +
                        (size_t)(ntile * 128 + o) * BB + b4;
            *(float4*)op = make_float4(v.x + bz, v.y + bz, v.z + bz, v.w + bz);
        }
    }
}

// ---------------- Phase 2: tensor-core persistent LSTM scan (unchanged) ------
__global__ void __launch_bounds__(256, 1)
lstm_scan_kernel(const float* __restrict__ Ui, const float* __restrict__ Uf,
                 const float* __restrict__ Uc, const float* __restrict__ Uo,
                 const float* __restrict__ bUf, const float* __restrict__ bUc,
                 const float* __restrict__ bUo,
                 float* __restrict__ outH, float* __restrict__ outC)
{
    extern __shared__ char smem[];
    const uint32_t sbase = (uint32_t)__cvta_generic_to_shared(smem);

    const int tid  = threadIdx.x;
    const int lane = tid & 31;
    const int warp = tid >> 5;
    const int kw = warp & 3;
    const int nh = warp >> 2;
    const int g  = blockIdx.x & 1;
    const int j0 = (blockIdx.x >> 1) * JPC;
    unsigned int* cnt = &g_cnt[g * 32];

    for (int idx = tid; idx < 32 * DD; idx += 256) {
        const int n = idx >> 9, k = idx & 511;
        const int gate = n >> 3, jl = n & 7;
        const float* U = (gate == 0) ? Ui : (gate == 1) ? Uf : (gate == 2) ? Uc : Uo;
        const float v = __ldg(&U[(size_t)(j0 + jl) * DD + k]);
        const __nv_bfloat16 hi = __float2bfloat16(v);
        const __nv_bfloat16 lo = __float2bfloat16(v - __bfloat162float(hi));
        *(__nv_bfloat16*)(smem + OFF_U1 + n * RSTRB + k * 2) = hi;
        *(__nv_bfloat16*)(smem + OFF_U2 + n * RSTRB + k * 2) = lo;
    }
    __syncthreads();

    uint32_t bc1[2][8][2], bc2[2][8][2];
    {
        const int brow = lane & 7;
        const int bsel = (lane >> 3) & 1;
#pragma unroll
        for (int nt = 0; nt < 2; nt++) {
            const int n0 = nh * 16 + nt * 8;
#pragma unroll
            for (int kt = 0; kt < 8; kt++) {
                const int k0 = kw * 128 + kt * 16;
                const uint32_t boff = (uint32_t)((n0 + brow) * RSTRB + (k0 + bsel * 8) * 2);
                ldsm_x2(bc1[nt][kt], sbase + OFF_U1 + boff);
                ldsm_x2(bc2[nt][kt], sbase + OFF_U2 + boff);
            }
        }
    }

    const int rA = (lane & 7) + ((lane >> 3) & 1) * 8;
    const int cA = (lane >> 4) * 8;
    const uint32_t aoff = (uint32_t)(rA * RSTRB + (kw * 128 + cA) * 2);

    const int jg = warp;
    const int bb = lane;
    const int jglob = j0 + jg;
    const int bglob = g * BPG + bb;
    const float bfb = __ldg(&bUf[jglob]);
    const float bcb = __ldg(&bUc[jglob]);
    const float bob = __ldg(&bUo[jglob]);

    float c = 0.f;
    float xi = __ldcg(&g_pre[0][(size_t)jglob * BB + bglob]);
    float xc = __ldcg(&g_pre[1][(size_t)jglob * BB + bglob]);
    float xo = __ldcg(&g_pre[2][(size_t)jglob * BB + bglob]);

    float* P  = (float*)(smem + OFF_P);
    float* HO = (float*)(smem + OFF_HO);
    float* CO = (float*)(smem + OFF_CO);

    for (int t = 0; t < TT; t++) {
        {
            const char* src = (const char*)&g_hs[g][t & 1][0][0][0];
#pragma unroll
            for (int i = 0; i < 16; i++) {
                const int m = tid + i * 256;
                const int s  = m >> 11;
                const int cc = m & 2047;
                const int b  = cc >> 6, kc = cc & 63;
                const uint32_t dst = sbase + (s ? OFF_H2 : OFF_H1) + b * RSTRB + kc * 16;
                cp16(dst, src + (size_t)s * (BPG * DD * 2) + b * (DD * 2) + kc * 16);
            }
            cp_wait_all();
        }
        __syncthreads();

        float acc[2][2][4] = {};
#pragma unroll
        for (int mt = 0; mt < 2; mt++) {
#pragma unroll
            for (int kt = 0; kt < 8; kt++) {
                uint32_t a1[4], a2[4];
                const uint32_t ao = mt * (16 * RSTRB) + kt * 32 + aoff;
                ldsm_x4(a1, sbase + OFF_H1 + ao);
                ldsm_x4(a2, sbase + OFF_H2 + ao);
#pragma unroll
                for (int nt = 0; nt < 2; nt++) {
                    mma_bf16(acc[mt][nt], a1, bc1[nt][kt]);
                    mma_bf16(acc[mt][nt], a2, bc1[nt][kt]);
                    mma_bf16(acc[mt][nt], a1, bc2[nt][kt]);
                    mma_bf16(acc[mt][nt], a2, bc2[nt][kt]);
                }
            }
        }

        {
            const int gq = lane >> 2, t2 = lane & 3;
#pragma unroll
            for (int mt = 0; mt < 2; mt++)
#pragma unroll
                for (int nt = 0; nt < 2; nt++) {
                    const int n0 = nh * 16 + nt * 8 + t2 * 2;
                    const int m0 = mt * 16 + gq;
                    *(float2*)&P[(kw * 32 + m0) * 34 + n0] =
                        make_float2(acc[mt][nt][0], acc[mt][nt][1]);
                    *(float2*)&P[(kw * 32 + m0 + 8) * 34 + n0] =
                        make_float2(acc[mt][nt][2], acc[mt][nt][3]);
                }
        }
        __syncthreads();

        float h;
        {
            float pre[4];
#pragma unroll
            for (int ga = 0; ga < 4; ga++) {
                const int n = ga * 8 + jg;
                pre[ga] = (P[(0 * 32 + bb) * 34 + n] + P[(1 * 32 + bb) * 34 + n]) +
                          (P[(2 * 32 + bb) * 34 + n] + P[(3 * 32 + bb) * 34 + n]);
            }
            const float pi = xi + pre[0];
            const float pf = xi + pre[1] + bfb;   // quirk: f uses xi
            const float pc = xc + pre[2] + bcb;
            const float po = xo + pre[3] + bob;
            const float ig = 1.f / (1.f + __expf(-pi));
            const float fg = 1.f / (1.f + __expf(-pf));
            const float gg = tanhf(pc);
            const float og = 1.f / (1.f + __expf(-po));
            c = fg * c + ig * gg;
            h = og * tanhf(c);

            const __nv_bfloat16 h1 = __float2bfloat16(h);
            const __nv_bfloat16 h2 = __float2bfloat16(h - __bfloat162float(h1));
            g_hs[g][(t + 1) & 1][0][bb][jglob] = *(const unsigned short*)&h1;
            g_hs[g][(t + 1) & 1][1][bb][jglob] = *(const unsigned short*)&h2;

            HO[bb * 9 + jg] = h;
            CO[bb * 9 + jg] = c;
        }
        __syncthreads();
        if (tid == 0) { __threadfence(); gbar_arrive(cnt); }

        {
            const int m = tid & 127;
            const int ob = m >> 2, oj = (m & 3) * 2;
            const size_t obase = (size_t)(g * BPG + ob) * (TT * DD) +
                                 (size_t)t * DD + j0 + oj;
            const float* S = (tid < 128) ? HO : CO;
            float* O = (tid < 128) ? outH : outC;
            *(float2*)&O[obase] = make_float2(S[ob * 9 + oj], S[ob * 9 + oj + 1]);
        }
        if (t + 1 < TT) {
            const size_t p2 = (size_t)(t + 1) * (DD * BB) + (size_t)jglob * BB + bglob;
            xi = __ldcg(&g_pre[0][p2]);
            xc = __ldcg(&g_pre[1][p2]);
            xo = __ldcg(&g_pre[2][p2]);
        }

        if (tid == 0) gbar_wait(cnt, (unsigned)(t + 1) * CPG);
        __syncthreads();
    }
}

// ---------------- launch -----------------------------------------------------
extern "C" void kernel_launch(void* const* d_in, const int* in_sizes, int n_in,
                              void* d_out, int out_size) {
    const float* X   = (const float*)d_in[0];
    const float* Wi  = (const float*)d_in[1];
    const float* bi  = (const float*)d_in[2];
    // d_in[3] = Wf, d_in[4] = bf: computed-but-unused in the reference
    const float* Wc  = (const float*)d_in[5];
    const float* bc  = (const float*)d_in[6];
    const float* Wo  = (const float*)d_in[7];
    const float* bo  = (const float*)d_in[8];
    const float* Ui  = (const float*)d_in[9];
    const float* Uf  = (const float*)d_in[10];
    const float* bUf = (const float*)d_in[11];
    const float* Uc  = (const float*)d_in[12];
    const float* bUc = (const float*)d_in[13];
    const float* Uo  = (const float*)d_in[14];
    const float* bUo = (const float*)d_in[15];

    float* outH = (float*)d_out;
    float* outC = outH + (size_t)BB * TT * DD;

    split_kernel<<<(BB * TT * (DD / 4) + 255) / 256, 256>>>(X, Wi, Wc, Wo);

    cudaFuncSetAttribute(gemm_tc_kernel,
                         cudaFuncAttributeMaxDynamicSharedMemorySize, SMEM_GEMM);
    dim3 g1(DD / 128, (BB * TT) / 128, 3);
    gemm_tc_kernel<<<g1, 256, SMEM_GEMM>>>(bi, bc, bo);

    cudaFuncSetAttribute(lstm_scan_kernel,
                         cudaFuncAttributeMaxDynamicSharedMemorySize, SMEM_SCAN);
    lstm_scan_kernel<<<NG * CPG, 256, SMEM_SCAN>>>(Ui, Uf, Uc, Uo, bUf, bUc, bUo,
                                                   outH, outC);
}